// round 3
// baseline (speedup 1.0000x reference)
#include <cuda_runtime.h>
#include <math.h>

// Problem constants
#define SEQ    2048
#define DIMC   1024
#define NH     16
#define HD     64
#define BATCH  4
#define BH     64          // BATCH*NH
#define TOK    8192        // BATCH*SEQ
#define NQKV   3072
#define QSCALE 0.125f      // 64^-0.5

// Scratch (allocation-free: __device__ globals)
__device__ float g_Q[(size_t)BH * SEQ * HD];
__device__ float g_K[(size_t)BH * SEQ * HD];
__device__ float g_V[(size_t)BH * SEQ * HD];
__device__ float g_AO[(size_t)TOK * DIMC];   // attention output, [B, N, C]

// ---------------------------------------------------------------------------
// Tiled SGEMM: C[M,N] = A[M,K] @ W[N,K]^T  (both row-major), 128x128x16 tiles,
// 256 threads, 8x8 per-thread register block.
// MODE 0: scatter into g_Q/g_K/g_V (Q pre-scaled).  MODE 1: +bias -> Cout.
// ---------------------------------------------------------------------------
template <int MODE>
__global__ __launch_bounds__(256) void gemm_kernel(
    const float* __restrict__ A, const float* __restrict__ W,
    const float* __restrict__ bias, float* __restrict__ Cout,
    int M, int N, int K)
{
    __shared__ float As[16][128];
    __shared__ float Bs[16][128];

    const int tid = threadIdx.x;
    const int tx = tid & 15;         // 0..15 -> 8 output cols each
    const int ty = tid >> 4;         // 0..15 -> 8 output rows each
    const int m0 = blockIdx.y << 7;
    const int n0 = blockIdx.x << 7;

    float acc[8][8];
#pragma unroll
    for (int j = 0; j < 8; j++)
#pragma unroll
        for (int i = 0; i < 8; i++) acc[j][i] = 0.f;

    for (int k0 = 0; k0 < K; k0 += 16) {
#pragma unroll
        for (int s = 0; s < 2; s++) {
            int slot = tid + (s << 8);       // 0..511 float4 slots
            int row  = slot >> 2;            // 0..127
            int c4   = (slot & 3) << 2;      // 0,4,8,12
            float4 va = *reinterpret_cast<const float4*>(
                A + (size_t)(m0 + row) * K + k0 + c4);
            As[c4 + 0][row] = va.x; As[c4 + 1][row] = va.y;
            As[c4 + 2][row] = va.z; As[c4 + 3][row] = va.w;
            float4 vb = *reinterpret_cast<const float4*>(
                W + (size_t)(n0 + row) * K + k0 + c4);
            Bs[c4 + 0][row] = vb.x; Bs[c4 + 1][row] = vb.y;
            Bs[c4 + 2][row] = vb.z; Bs[c4 + 3][row] = vb.w;
        }
        __syncthreads();
#pragma unroll
        for (int kk = 0; kk < 16; kk++) {
            float a[8], b[8];
            *reinterpret_cast<float4*>(a)     = *reinterpret_cast<const float4*>(&As[kk][ty * 8]);
            *reinterpret_cast<float4*>(a + 4) = *reinterpret_cast<const float4*>(&As[kk][ty * 8 + 4]);
            *reinterpret_cast<float4*>(b)     = *reinterpret_cast<const float4*>(&Bs[kk][tx * 8]);
            *reinterpret_cast<float4*>(b + 4) = *reinterpret_cast<const float4*>(&Bs[kk][tx * 8 + 4]);
#pragma unroll
            for (int j = 0; j < 8; j++)
#pragma unroll
                for (int i = 0; i < 8; i++) acc[j][i] += a[j] * b[i];
        }
        __syncthreads();
    }

    if (MODE == 0) {
        // scatter qkv: col c -> (which, head, d); row m -> (batch, n)
#pragma unroll
        for (int j = 0; j < 8; j++) {
            int m = m0 + ty * 8 + j;
            int bb = m >> 11, n = m & (SEQ - 1);
#pragma unroll
            for (int i = 0; i < 8; i++) {
                int c = n0 + tx * 8 + i;
                int which = c >> 10;
                int h = (c & 1023) >> 6;
                int d = c & 63;
                size_t idx = ((size_t)(bb * NH + h) * SEQ + n) * HD + d;
                float v = acc[j][i];
                if (which == 0)      g_Q[idx] = v * QSCALE;
                else if (which == 1) g_K[idx] = v;
                else                 g_V[idx] = v;
            }
        }
    } else {
#pragma unroll
        for (int j = 0; j < 8; j++) {
            int m = m0 + ty * 8 + j;
#pragma unroll
            for (int i = 0; i < 8; i++) {
                int c = n0 + tx * 8 + i;
                Cout[(size_t)m * N + c] = acc[j][i] + bias[c];
            }
        }
    }
}

// ---------------------------------------------------------------------------
// Flash-style attention: one block per (bh, 64-query tile). 256 threads (16x16),
// each thread owns a 4(q) x 4 register block. KV streamed in 64-row tiles.
// Smem layouts (stride 68 floats = 272B, 16B aligned):
//   Qs [d][q]  transposed     Ks [d][kv] transposed
//   Vs [kv][d] natural        Ps [kv][q] transposed
// ---------------------------------------------------------------------------
#define APAD 68
#define SMEM_ATTN (4 * 64 * APAD * sizeof(float))

__global__ __launch_bounds__(256) void attn_kernel()
{
    extern __shared__ float sm[];
    float* Qs = sm;
    float* Ks = sm + 64 * APAD;
    float* Vs = sm + 2 * 64 * APAD;
    float* Ps = sm + 3 * 64 * APAD;

    const int tid = threadIdx.x;
    const int tx = tid & 15;      // 4 cols (kv in S-phase / d in O-phase)
    const int ty = tid >> 4;      // 4 query rows
    const int bh = blockIdx.y;
    const int q0 = blockIdx.x << 6;

    const float* Qp = g_Q + (size_t)bh * SEQ * HD;
    const float* Kp = g_K + (size_t)bh * SEQ * HD;
    const float* Vp = g_V + (size_t)bh * SEQ * HD;

    // Load Q tile, transposed into Qs[d][q]
#pragma unroll
    for (int s = 0; s < 4; s++) {
        int slot = tid + (s << 8);        // 0..1023 float4 slots
        int r = slot >> 4;                // 0..63 (q row)
        int c = (slot & 15) << 2;         // 0..60 (d)
        float4 v = *reinterpret_cast<const float4*>(Qp + (size_t)(q0 + r) * HD + c);
        Qs[(c + 0) * APAD + r] = v.x; Qs[(c + 1) * APAD + r] = v.y;
        Qs[(c + 2) * APAD + r] = v.z; Qs[(c + 3) * APAD + r] = v.w;
    }

    float o[4][4];
    float mi[4], li[4];
#pragma unroll
    for (int j = 0; j < 4; j++) {
        mi[j] = -1e30f; li[j] = 0.f;
#pragma unroll
        for (int i = 0; i < 4; i++) o[j][i] = 0.f;
    }

    for (int kt = 0; kt < SEQ / 64; kt++) {
        __syncthreads();   // previous tile's smem reads complete
        const float* Kt = Kp + (size_t)kt * 64 * HD;
        const float* Vt = Vp + (size_t)kt * 64 * HD;
#pragma unroll
        for (int s = 0; s < 4; s++) {
            int slot = tid + (s << 8);
            int r = slot >> 4;
            int c = (slot & 15) << 2;
            float4 v = *reinterpret_cast<const float4*>(Kt + (size_t)r * HD + c);
            Ks[(c + 0) * APAD + r] = v.x; Ks[(c + 1) * APAD + r] = v.y;
            Ks[(c + 2) * APAD + r] = v.z; Ks[(c + 3) * APAD + r] = v.w;
            float4 w = *reinterpret_cast<const float4*>(Vt + (size_t)r * HD + c);
            *reinterpret_cast<float4*>(&Vs[r * APAD + c]) = w;
        }
        __syncthreads();

        // S = Q @ K^T (Q pre-scaled)
        float s4[4][4];
#pragma unroll
        for (int j = 0; j < 4; j++)
#pragma unroll
            for (int i = 0; i < 4; i++) s4[j][i] = 0.f;
#pragma unroll
        for (int d = 0; d < 64; d++) {
            float4 av = *reinterpret_cast<const float4*>(&Qs[d * APAD + ty * 4]);
            float4 bv = *reinterpret_cast<const float4*>(&Ks[d * APAD + tx * 4]);
            const float a[4] = {av.x, av.y, av.z, av.w};
            const float b[4] = {bv.x, bv.y, bv.z, bv.w};
#pragma unroll
            for (int j = 0; j < 4; j++)
#pragma unroll
                for (int i = 0; i < 4; i++) s4[j][i] += a[j] * b[i];
        }

        // online softmax per query row; write P transposed into Ps[kv][q]
#pragma unroll
        for (int j = 0; j < 4; j++) {
            float rm = fmaxf(fmaxf(s4[j][0], s4[j][1]), fmaxf(s4[j][2], s4[j][3]));
#pragma unroll
            for (int off = 8; off >= 1; off >>= 1)
                rm = fmaxf(rm, __shfl_xor_sync(0xffffffffu, rm, off));
            float mnew = fmaxf(mi[j], rm);
            float corr = __expf(mi[j] - mnew);
            mi[j] = mnew;
            li[j] *= corr;
#pragma unroll
            for (int i = 0; i < 4; i++) o[j][i] *= corr;
            float rs = 0.f;
#pragma unroll
            for (int i = 0; i < 4; i++) {
                float p = __expf(s4[j][i] - mnew);
                Ps[(tx * 4 + i) * APAD + ty * 4 + j] = p;
                rs += p;
            }
#pragma unroll
            for (int off = 8; off >= 1; off >>= 1)
                rs += __shfl_xor_sync(0xffffffffu, rs, off);
            li[j] += rs;
        }
        __syncthreads();

        // O += P @ V
#pragma unroll
        for (int kv = 0; kv < 64; kv++) {
            float4 av = *reinterpret_cast<const float4*>(&Ps[kv * APAD + ty * 4]);
            float4 bv = *reinterpret_cast<const float4*>(&Vs[kv * APAD + tx * 4]);
            const float a[4] = {av.x, av.y, av.z, av.w};
            const float b[4] = {bv.x, bv.y, bv.z, bv.w};
#pragma unroll
            for (int j = 0; j < 4; j++)
#pragma unroll
                for (int i = 0; i < 4; i++) o[j][i] += a[j] * b[i];
        }
    }

    // epilogue: normalize, write [B, N, C]
    const int bb = bh >> 4, h = bh & 15;
#pragma unroll
    for (int j = 0; j < 4; j++) {
        int n = q0 + ty * 4 + j;
        float inv = 1.f / li[j];
#pragma unroll
        for (int i = 0; i < 4; i++) {
            int c = h * HD + tx * 4 + i;
            g_AO[((size_t)(bb * SEQ + n)) * DIMC + c] = o[j][i] * inv;
        }
    }
}

// ---------------------------------------------------------------------------
extern "C" void kernel_launch(void* const* d_in, const int* in_sizes, int n_in,
                              void* d_out, int out_size)
{
    const float* x      = (const float*)d_in[0];
    const float* w_qkv  = (const float*)d_in[1];
    const float* w_proj = (const float*)d_in[2];
    const float* b_proj = (const float*)d_in[3];
    float* out = (float*)d_out;

    float* pAO = nullptr;
    cudaGetSymbolAddress((void**)&pAO, g_AO);

    cudaFuncSetAttribute(attn_kernel,
                         cudaFuncAttributeMaxDynamicSharedMemorySize,
                         (int)SMEM_ATTN);

    dim3 g1(NQKV / 128, TOK / 128);      // (24, 64)
    gemm_kernel<0><<<g1, 256>>>(x, w_qkv, nullptr, nullptr, TOK, NQKV, DIMC);

    dim3 ga(SEQ / 64, BH);               // (32, 64)
    attn_kernel<<<ga, 256, SMEM_ATTN>>>();

    dim3 g2(DIMC / 128, TOK / 128);      // (8, 64)
    gemm_kernel<1><<<g2, 256>>>(pAO, w_proj, b_proj, out, TOK, DIMC, DIMC);
}

// round 8
// speedup vs baseline: 2.5166x; 2.5166x over previous
#include <cuda_runtime.h>
#include <cuda_bf16.h>
#include <cstdint>
#include <math.h>

// Problem constants
#define SEQ    2048
#define DIMC   1024
#define NH     16
#define HD     64
#define BATCH  4
#define BH     64          // BATCH*NH
#define TOK    8192        // BATCH*SEQ
#define NQKV   3072
#define QSCALE 0.125f      // 64^-0.5

// Scratch (allocation-free: __device__ globals)
__device__ float g_Q[(size_t)BH * SEQ * HD];
__device__ float g_K[(size_t)BH * SEQ * HD];
__device__ float g_V[(size_t)BH * SEQ * HD];
__device__ float g_AO[(size_t)TOK * DIMC];   // attention output, [B, N, C]

// ===========================================================================
// mma.sync / ldmatrix helpers (legal on base sm_103 target)
// ===========================================================================
__device__ __forceinline__ uint32_t smem_u32(const void* p) {
    uint32_t a;
    asm("{ .reg .u64 t; cvta.to.shared.u64 t, %1; cvt.u32.u64 %0, t; }"
        : "=r"(a) : "l"(p));
    return a;
}
__device__ __forceinline__ void mma_bf16(float* c, const uint32_t* a, const uint32_t* b) {
    asm volatile(
        "mma.sync.aligned.m16n8k16.row.col.f32.bf16.bf16.f32 "
        "{%0,%1,%2,%3}, {%4,%5,%6,%7}, {%8,%9}, {%0,%1,%2,%3};"
        : "+f"(c[0]), "+f"(c[1]), "+f"(c[2]), "+f"(c[3])
        : "r"(a[0]), "r"(a[1]), "r"(a[2]), "r"(a[3]), "r"(b[0]), "r"(b[1]));
}
__device__ __forceinline__ void ldsm4(uint32_t* r, uint32_t addr) {
    asm volatile("ldmatrix.sync.aligned.m8n8.x4.shared.b16 {%0,%1,%2,%3}, [%4];"
                 : "=r"(r[0]), "=r"(r[1]), "=r"(r[2]), "=r"(r[3]) : "r"(addr));
}
__device__ __forceinline__ void ldsm2(uint32_t* r, uint32_t addr) {
    asm volatile("ldmatrix.sync.aligned.m8n8.x2.shared.b16 {%0,%1}, [%2];"
                 : "=r"(r[0]), "=r"(r[1]) : "r"(addr));
}
__device__ __forceinline__ void ldsm2t(uint32_t* r, uint32_t addr) {
    asm volatile("ldmatrix.sync.aligned.m8n8.x2.trans.shared.b16 {%0,%1}, [%2];"
                 : "=r"(r[0]), "=r"(r[1]) : "r"(addr));
}
// pack two fp32 -> bf16x2 reg (lo = first arg, hi = second arg)
__device__ __forceinline__ uint32_t pack2(float lo, float hi) {
    uint32_t r;
    asm("cvt.rn.bf16x2.f32 %0, %1, %2;" : "=r"(r) : "f"(hi), "f"(lo));
    return r;
}
// hi = bf16 round of v (as float); returns hi
__device__ __forceinline__ float bhi(float v) {
    return __bfloat162float(__float2bfloat16(v));
}

// ===========================================================================
// bf16x3 tensor-core GEMM: C[M,N] = A[M,K] @ W[N,K]^T, both row-major.
// 128x128 CTA tile, 256 threads, 8 warps (4 along M x 2 along N):
// each warp 32(m) x 64(n) = 2 m16-tiles x 8 n8-tiles. K chunked by 32.
// MODE 0: scatter -> g_Q/g_K/g_V (Q pre-scaled).  MODE 1: +bias -> Cout.
// ===========================================================================
#define GST 40   // smem row stride in bf16 (80B: conflict-free for ldmatrix)

template <int MODE>
__global__ __launch_bounds__(256) void gemm_mma(
    const float* __restrict__ A, const float* __restrict__ W,
    const float* __restrict__ bias, float* __restrict__ Cout,
    int M, int N, int K)
{
    __shared__ __align__(16) __nv_bfloat16 sAh[128][GST];
    __shared__ __align__(16) __nv_bfloat16 sAl[128][GST];
    __shared__ __align__(16) __nv_bfloat16 sBh[128][GST];
    __shared__ __align__(16) __nv_bfloat16 sBl[128][GST];

    const int tid = threadIdx.x;
    const int lid = tid & 31;
    const int wid = tid >> 5;
    const int wm = wid & 3;          // warp row (32 m-rows each)
    const int wn = wid >> 2;         // warp col (64 n-cols each)
    const int m0 = blockIdx.y << 7;
    const int n0 = blockIdx.x << 7;

    float acc[2][8][4];
#pragma unroll
    for (int i = 0; i < 2; i++)
#pragma unroll
        for (int j = 0; j < 8; j++)
#pragma unroll
            for (int v = 0; v < 4; v++) acc[i][j][v] = 0.f;

    const int nchunks = K >> 5;
#pragma unroll 1
    for (int t = 0; t < nchunks; ++t) {
        const int k0 = t << 5;
        // load + split 128x32 fp32 of A and B into bf16 hi/lo smem
#pragma unroll
        for (int it = 0; it < 4; it++) {
            int slot = tid + (it << 8);      // 1024 slots
            int r  = slot >> 3;              // 0..127
            int cf = (slot & 7) << 2;        // 0..28
            float4 va = *reinterpret_cast<const float4*>(
                A + (size_t)(m0 + r) * K + k0 + cf);
            float hx = bhi(va.x), hy = bhi(va.y), hz = bhi(va.z), hw = bhi(va.w);
            uint2 uh = { pack2(hx, hy), pack2(hz, hw) };
            uint2 ul = { pack2(va.x - hx, va.y - hy), pack2(va.z - hz, va.w - hw) };
            *reinterpret_cast<uint2*>(&sAh[r][cf]) = uh;
            *reinterpret_cast<uint2*>(&sAl[r][cf]) = ul;
            float4 vb = *reinterpret_cast<const float4*>(
                W + (size_t)(n0 + r) * K + k0 + cf);
            hx = bhi(vb.x); hy = bhi(vb.y); hz = bhi(vb.z); hw = bhi(vb.w);
            uh.x = pack2(hx, hy); uh.y = pack2(hz, hw);
            ul.x = pack2(vb.x - hx, vb.y - hy); ul.y = pack2(vb.z - hz, vb.w - hw);
            *reinterpret_cast<uint2*>(&sBh[r][cf]) = uh;
            *reinterpret_cast<uint2*>(&sBl[r][cf]) = ul;
        }
        __syncthreads();

#pragma unroll
        for (int ks = 0; ks < 2; ks++) {
            uint32_t ah[2][4], al[2][4], bh[8][2], bl[8][2];
#pragma unroll
            for (int i = 0; i < 2; i++) {
                int r = wm * 32 + i * 16 + (lid & 15);
                int c = ks * 16 + (lid >> 4) * 8;
                ldsm4(ah[i], smem_u32(&sAh[r][c]));
                ldsm4(al[i], smem_u32(&sAl[r][c]));
            }
#pragma unroll
            for (int j = 0; j < 8; j++) {
                int r = wn * 64 + j * 8 + (lid & 7);
                int c = ks * 16 + ((lid >> 3) & 1) * 8;
                ldsm2(bh[j], smem_u32(&sBh[r][c]));
                ldsm2(bl[j], smem_u32(&sBl[r][c]));
            }
#pragma unroll
            for (int i = 0; i < 2; i++)
#pragma unroll
                for (int j = 0; j < 8; j++) {
                    mma_bf16(acc[i][j], ah[i], bh[j]);
                    mma_bf16(acc[i][j], ah[i], bl[j]);
                    mma_bf16(acc[i][j], al[i], bh[j]);
                }
        }
        __syncthreads();
    }

    // epilogue
    const int qr = lid >> 2, qc = (lid & 3) << 1;
#pragma unroll
    for (int i = 0; i < 2; i++) {
#pragma unroll
        for (int j = 0; j < 8; j++) {
            int r0 = m0 + wm * 32 + i * 16 + qr;
            int c  = n0 + wn * 64 + j * 8 + qc;
#pragma unroll
            for (int hh = 0; hh < 2; hh++) {
                int m = r0 + hh * 8;
                float v0 = acc[i][j][2 * hh], v1 = acc[i][j][2 * hh + 1];
                if (MODE == 0) {
                    int bb = m >> 11, n = m & (SEQ - 1);
                    int which = c >> 10, cc = c & 1023;
                    int hd = cc >> 6, d = cc & 63;
                    size_t idx = ((size_t)(bb * NH + hd) * SEQ + n) * HD + d;
                    float2 v;
                    if (which == 0) { v.x = v0 * QSCALE; v.y = v1 * QSCALE;
                        *reinterpret_cast<float2*>(&g_Q[idx]) = v; }
                    else if (which == 1) { v.x = v0; v.y = v1;
                        *reinterpret_cast<float2*>(&g_K[idx]) = v; }
                    else { v.x = v0; v.y = v1;
                        *reinterpret_cast<float2*>(&g_V[idx]) = v; }
                } else {
                    float2 bv = *reinterpret_cast<const float2*>(bias + c);
                    float2 v = { v0 + bv.x, v1 + bv.y };
                    *reinterpret_cast<float2*>(Cout + (size_t)m * N + c) = v;
                }
            }
        }
    }
}

// ===========================================================================
// bf16x3 tensor-core flash attention.
// CTA: 128 q-rows, 8 warps (16 q-rows each, full kv tile), 64-row KV tiles.
// Q frags register-resident (hi/lo). S and O in mma C-fragments. Online
// softmax via quad shuffles. P repacked directly into A-frags. V via
// ldmatrix.trans.
// ===========================================================================
#define AST 72   // attention smem row stride in bf16 (144B: conflict-free)

__global__ __launch_bounds__(256) void attn_mma()
{
    // Q staging (128x72 hi+lo) and K/V tiles (4 x 64x72) both = 36864 B
    __shared__ __align__(16) __nv_bfloat16 sbuf[2 * 128 * AST];
    __nv_bfloat16* Kh = sbuf;
    __nv_bfloat16* Kl = sbuf + 64 * AST;
    __nv_bfloat16* Vh = sbuf + 2 * 64 * AST;
    __nv_bfloat16* Vl = sbuf + 3 * 64 * AST;
    __nv_bfloat16* Qh = sbuf;                 // staging (overwritten later)
    __nv_bfloat16* Ql = sbuf + 128 * AST;

    const int tid = threadIdx.x;
    const int lid = tid & 31;
    const int w   = tid >> 5;
    const int bh  = blockIdx.y;
    const int q0  = blockIdx.x << 7;

    const float* Qp = g_Q + (size_t)bh * SEQ * HD;
    const float* Kp = g_K + (size_t)bh * SEQ * HD;
    const float* Vp = g_V + (size_t)bh * SEQ * HD;

    // ---- stage Q (128x64) into smem hi/lo, then lift to registers ----
#pragma unroll
    for (int it = 0; it < 8; it++) {
        int slot = tid + (it << 8);        // 2048 slots
        int r  = slot >> 4;                // 0..127
        int cf = (slot & 15) << 2;         // 0..60
        float4 v = *reinterpret_cast<const float4*>(Qp + (size_t)(q0 + r) * HD + cf);
        float hx = bhi(v.x), hy = bhi(v.y), hz = bhi(v.z), hw = bhi(v.w);
        uint2 uh = { pack2(hx, hy), pack2(hz, hw) };
        uint2 ul = { pack2(v.x - hx, v.y - hy), pack2(v.z - hz, v.w - hw) };
        *reinterpret_cast<uint2*>(&Qh[r * AST + cf]) = uh;
        *reinterpret_cast<uint2*>(&Ql[r * AST + cf]) = ul;
    }
    __syncthreads();

    uint32_t qh[4][4], ql[4][4];
#pragma unroll
    for (int k4 = 0; k4 < 4; k4++) {
        int r = w * 16 + (lid & 15);
        int c = k4 * 16 + (lid >> 4) * 8;
        ldsm4(qh[k4], smem_u32(&Qh[r * AST + c]));
        ldsm4(ql[k4], smem_u32(&Ql[r * AST + c]));
    }
    __syncthreads();   // done reading Q staging; smem now free for K/V

    float o[8][4];
#pragma unroll
    for (int j = 0; j < 8; j++)
#pragma unroll
        for (int v = 0; v < 4; v++) o[j][v] = 0.f;
    float mrow[2] = { -1e30f, -1e30f };
    float lrow[2] = { 0.f, 0.f };

#pragma unroll 1
    for (int kt = 0; kt < SEQ / 64; kt++) {
        // ---- load K/V tile (64x64 each), split to bf16 hi/lo ----
        const float* Kt = Kp + (size_t)(kt * 64) * HD;
        const float* Vt = Vp + (size_t)(kt * 64) * HD;
#pragma unroll
        for (int it = 0; it < 4; it++) {
            int slot = tid + (it << 8);    // 1024 slots
            int r  = slot >> 4;            // 0..63
            int cf = (slot & 15) << 2;     // 0..60
            float4 v = *reinterpret_cast<const float4*>(Kt + (size_t)r * HD + cf);
            float hx = bhi(v.x), hy = bhi(v.y), hz = bhi(v.z), hw = bhi(v.w);
            uint2 uh = { pack2(hx, hy), pack2(hz, hw) };
            uint2 ul = { pack2(v.x - hx, v.y - hy), pack2(v.z - hz, v.w - hw) };
            *reinterpret_cast<uint2*>(&Kh[r * AST + cf]) = uh;
            *reinterpret_cast<uint2*>(&Kl[r * AST + cf]) = ul;
            v = *reinterpret_cast<const float4*>(Vt + (size_t)r * HD + cf);
            hx = bhi(v.x); hy = bhi(v.y); hz = bhi(v.z); hw = bhi(v.w);
            uh.x = pack2(hx, hy); uh.y = pack2(hz, hw);
            ul.x = pack2(v.x - hx, v.y - hy); ul.y = pack2(v.z - hz, v.w - hw);
            *reinterpret_cast<uint2*>(&Vh[r * AST + cf]) = uh;
            *reinterpret_cast<uint2*>(&Vl[r * AST + cf]) = ul;
        }
        __syncthreads();

        // ---- S = Q @ K^T  (bf16x3), 8 kv n-tiles x 4 d k-steps ----
        float s[8][4];
#pragma unroll
        for (int j = 0; j < 8; j++)
#pragma unroll
            for (int v = 0; v < 4; v++) s[j][v] = 0.f;
#pragma unroll
        for (int j = 0; j < 8; j++) {
#pragma unroll
            for (int k4 = 0; k4 < 4; k4++) {
                int r = j * 8 + (lid & 7);
                int c = k4 * 16 + ((lid >> 3) & 1) * 8;
                uint32_t kh[2], kl[2];
                ldsm2(kh, smem_u32(&Kh[r * AST + c]));
                ldsm2(kl, smem_u32(&Kl[r * AST + c]));
                mma_bf16(s[j], qh[k4], kh);
                mma_bf16(s[j], qh[k4], kl);
                mma_bf16(s[j], ql[k4], kh);
            }
        }

        // ---- online softmax (per row-half; rows qr and qr+8) ----
#pragma unroll
        for (int hh = 0; hh < 2; hh++) {
            float rm = -1e30f;
#pragma unroll
            for (int j = 0; j < 8; j++)
                rm = fmaxf(rm, fmaxf(s[j][2 * hh], s[j][2 * hh + 1]));
            rm = fmaxf(rm, __shfl_xor_sync(0xffffffffu, rm, 1));
            rm = fmaxf(rm, __shfl_xor_sync(0xffffffffu, rm, 2));
            float mnew = fmaxf(mrow[hh], rm);
            float corr = __expf(mrow[hh] - mnew);
            mrow[hh] = mnew;
            float ls = lrow[hh] * corr;
#pragma unroll
            for (int j = 0; j < 8; j++) {
                float p0 = __expf(s[j][2 * hh]     - mnew);
                float p1 = __expf(s[j][2 * hh + 1] - mnew);
                s[j][2 * hh] = p0; s[j][2 * hh + 1] = p1;
                ls += p0 + p1;
                o[j][2 * hh]     *= corr;
                o[j][2 * hh + 1] *= corr;
            }
            lrow[hh] = ls;
        }

        // ---- repack P into A-frags (hi/lo), register-direct ----
        uint32_t ph[4][4], pl[4][4];
#pragma unroll
        for (int t = 0; t < 4; t++) {
#pragma unroll
            for (int half = 0; half < 2; half++) {    // a0/a1 from tile 2t, a2/a3 from 2t+1
                const float* sv = s[2 * t + half];
#pragma unroll
                for (int hh = 0; hh < 2; hh++) {
                    float p0 = sv[2 * hh], p1 = sv[2 * hh + 1];
                    float h0 = bhi(p0), h1 = bhi(p1);
                    ph[t][2 * half + hh] = pack2(h0, h1);
                    pl[t][2 * half + hh] = pack2(p0 - h0, p1 - h1);
                }
            }
        }
        // A-frag order fix: a0=(r,klo), a1=(r+8,klo), a2=(r,khi), a3=(r+8,khi)
        // built above as [tile2t: hh0, hh1][tile2t+1: hh0, hh1] == [a0,a1,a2,a3]  ✓

        // ---- O += P @ V  (bf16x3), 8 d n-tiles x 4 kv k-steps ----
#pragma unroll
        for (int j = 0; j < 8; j++) {
#pragma unroll
            for (int t = 0; t < 4; t++) {
                int r = t * 16 + (lid & 15);
                int c = j * 8;
                uint32_t vh[2], vl[2];
                ldsm2t(vh, smem_u32(&Vh[r * AST + c]));
                ldsm2t(vl, smem_u32(&Vl[r * AST + c]));
                mma_bf16(o[j], ph[t], vh);
                mma_bf16(o[j], ph[t], vl);
                mma_bf16(o[j], pl[t], vh);
            }
        }
        __syncthreads();
    }

    // ---- epilogue: reduce l across quad, normalize, write [B,N,C] ----
#pragma unroll
    for (int hh = 0; hh < 2; hh++) {
        lrow[hh] += __shfl_xor_sync(0xffffffffu, lrow[hh], 1);
        lrow[hh] += __shfl_xor_sync(0xffffffffu, lrow[hh], 2);
    }
    const int bb = bh >> 4, hd = bh & 15;
    const int qr = lid >> 2, qc = (lid & 3) << 1;
#pragma unroll
    for (int hh = 0; hh < 2; hh++) {
        float inv = 1.f / lrow[hh];
        int n = q0 + w * 16 + qr + hh * 8;
        float* dst = g_AO + ((size_t)(bb * SEQ + n)) * DIMC + hd * HD;
#pragma unroll
        for (int j = 0; j < 8; j++) {
            float2 v = { o[j][2 * hh] * inv, o[j][2 * hh + 1] * inv };
            *reinterpret_cast<float2*>(dst + j * 8 + qc) = v;
        }
    }
}

// ---------------------------------------------------------------------------
extern "C" void kernel_launch(void* const* d_in, const int* in_sizes, int n_in,
                              void* d_out, int out_size)
{
    const float* x      = (const float*)d_in[0];
    const float* w_qkv  = (const float*)d_in[1];
    const float* w_proj = (const float*)d_in[2];
    const float* b_proj = (const float*)d_in[3];
    float* out = (float*)d_out;

    float* pAO = nullptr;
    cudaGetSymbolAddress((void**)&pAO, g_AO);

    dim3 g1(NQKV / 128, TOK / 128);      // (24, 64)
    gemm_mma<0><<<g1, 256>>>(x, w_qkv, nullptr, nullptr, TOK, NQKV, DIMC);

    dim3 ga(SEQ / 128, BH);              // (16, 64)
    attn_mma<<<ga, 256>>>();

    dim3 g2(DIMC / 128, TOK / 128);      // (8, 64)
    gemm_mma<1><<<g2, 256>>>(pAO, w_proj, b_proj, out, TOK, DIMC, DIMC);
}

// round 9
// speedup vs baseline: 2.7955x; 1.1108x over previous
#include <cuda_runtime.h>
#include <cuda_bf16.h>
#include <cstdint>
#include <math.h>

// Problem constants
#define SEQ    2048
#define DIMC   1024
#define NH     16
#define HD     64
#define BATCH  4
#define BH     64          // BATCH*NH
#define TOK    8192        // BATCH*SEQ
#define NQKV   3072
#define QSCALE 0.125f      // 64^-0.5

// Persistent bf16 hi/lo scratch (allocation-free: __device__ globals)
__device__ __nv_bfloat16 g_Xh[(size_t)TOK * DIMC],  g_Xl[(size_t)TOK * DIMC];
__device__ __nv_bfloat16 g_Wqh[(size_t)NQKV * DIMC], g_Wql[(size_t)NQKV * DIMC];
__device__ __nv_bfloat16 g_Wph[(size_t)DIMC * DIMC], g_Wpl[(size_t)DIMC * DIMC];
__device__ __nv_bfloat16 g_Qh[(size_t)BH * SEQ * HD], g_Ql[(size_t)BH * SEQ * HD];
__device__ __nv_bfloat16 g_Kh[(size_t)BH * SEQ * HD], g_Kl[(size_t)BH * SEQ * HD];
__device__ __nv_bfloat16 g_Vh[(size_t)BH * SEQ * HD], g_Vl[(size_t)BH * SEQ * HD];
__device__ __nv_bfloat16 g_AOh[(size_t)TOK * DIMC],  g_AOl[(size_t)TOK * DIMC];

// ===========================================================================
// helpers (legal on base sm_103 target: mma.sync / ldmatrix / cp.async)
// ===========================================================================
__device__ __forceinline__ uint32_t smem_u32(const void* p) {
    uint32_t a;
    asm("{ .reg .u64 t; cvta.to.shared.u64 t, %1; cvt.u32.u64 %0, t; }"
        : "=r"(a) : "l"(p));
    return a;
}
__device__ __forceinline__ void mma_bf16(float* c, const uint32_t* a, const uint32_t* b) {
    asm volatile(
        "mma.sync.aligned.m16n8k16.row.col.f32.bf16.bf16.f32 "
        "{%0,%1,%2,%3}, {%4,%5,%6,%7}, {%8,%9}, {%0,%1,%2,%3};"
        : "+f"(c[0]), "+f"(c[1]), "+f"(c[2]), "+f"(c[3])
        : "r"(a[0]), "r"(a[1]), "r"(a[2]), "r"(a[3]), "r"(b[0]), "r"(b[1]));
}
__device__ __forceinline__ void ldsm4(uint32_t* r, uint32_t addr) {
    asm volatile("ldmatrix.sync.aligned.m8n8.x4.shared.b16 {%0,%1,%2,%3}, [%4];"
                 : "=r"(r[0]), "=r"(r[1]), "=r"(r[2]), "=r"(r[3]) : "r"(addr));
}
__device__ __forceinline__ void ldsm4t(uint32_t* r, uint32_t addr) {
    asm volatile("ldmatrix.sync.aligned.m8n8.x4.trans.shared.b16 {%0,%1,%2,%3}, [%4];"
                 : "=r"(r[0]), "=r"(r[1]), "=r"(r[2]), "=r"(r[3]) : "r"(addr));
}
__device__ __forceinline__ void cp16(uint32_t dst, const void* src) {
    asm volatile("cp.async.cg.shared.global [%0], [%1], 16;" :: "r"(dst), "l"(src));
}
#define CP_COMMIT()  asm volatile("cp.async.commit_group;" ::: "memory")
#define CP_WAIT0()   asm volatile("cp.async.wait_group 0;" ::: "memory")
#define CP_WAIT1()   asm volatile("cp.async.wait_group 1;" ::: "memory")

// pack two fp32 -> bf16x2 reg (lo lane = first arg)
__device__ __forceinline__ uint32_t pack2(float lo, float hi) {
    uint32_t r;
    asm("cvt.rn.bf16x2.f32 %0, %1, %2;" : "=r"(r) : "f"(hi), "f"(lo));
    return r;
}
__device__ __forceinline__ float bhi(float v) {
    return __bfloat162float(__float2bfloat16(v));
}

// ===========================================================================
// split kernel: fp32 -> bf16 hi + bf16 lo (residual)
// ===========================================================================
__global__ __launch_bounds__(256) void split_kernel(
    const float* __restrict__ in, __nv_bfloat16* __restrict__ oh,
    __nv_bfloat16* __restrict__ ol, int n4)
{
    int i = blockIdx.x * blockDim.x + threadIdx.x;
    if (i >= n4) return;
    float4 v = reinterpret_cast<const float4*>(in)[i];
    float hx = bhi(v.x), hy = bhi(v.y), hz = bhi(v.z), hw = bhi(v.w);
    uint2 uh = { pack2(hx, hy), pack2(hz, hw) };
    uint2 ul = { pack2(v.x - hx, v.y - hy), pack2(v.z - hz, v.w - hw) };
    reinterpret_cast<uint2*>(oh)[i] = uh;
    reinterpret_cast<uint2*>(ol)[i] = ul;
}

// ===========================================================================
// bf16x3 GEMM on pre-split operands: C = A @ W^T, A[M,K], W[N,K] row-major.
// 128x128 CTA, 256 threads (8 warps: 4 along M x 2 along N), K chunks of 32,
// cp.async double-buffered smem. MODE 0: scatter hi/lo -> Q/K/V.
// MODE 1: +bias -> fp32 Cout.
// ===========================================================================
#define GST       40                       // smem row stride (bf16): 80B
#define GBUF      (128 * GST * 2)          // 10240 B per operand buffer
#define GSTAGE    (4 * GBUF)               // 40960 B per stage
#define SMEM_GEMM (2 * GSTAGE)             // 81920 B

__device__ __forceinline__ void gemm_cp(
    uint32_t stage, const __nv_bfloat16* Ah, const __nv_bfloat16* Al,
    const __nv_bfloat16* Bh, const __nv_bfloat16* Bl,
    int m0, int n0, int k0, int K, int tid)
{
#pragma unroll
    for (int it = 0; it < 8; it++) {
        int slot = tid + (it << 8);          // 0..2047
        int buf  = slot >> 9;                // 0:Ah 1:Al 2:Bh 3:Bl
        int s2   = slot & 511;
        int r    = s2 >> 2;                  // 0..127
        int c16  = s2 & 3;                   // 0..3 (16B units)
        const __nv_bfloat16* base = (buf == 0) ? Ah : (buf == 1) ? Al
                                  : (buf == 2) ? Bh : Bl;
        int row = ((buf < 2) ? m0 : n0) + r;
        cp16(stage + buf * GBUF + r * (GST * 2) + c16 * 16,
             base + (size_t)row * K + k0 + c16 * 8);
    }
}

template <int MODE>
__global__ __launch_bounds__(256) void gemm_mma(
    const __nv_bfloat16* __restrict__ Ah, const __nv_bfloat16* __restrict__ Al,
    const __nv_bfloat16* __restrict__ Bh, const __nv_bfloat16* __restrict__ Bl,
    const float* __restrict__ bias, float* __restrict__ Cout,
    int M, int N, int K)
{
    extern __shared__ __align__(16) char smg[];
    const uint32_t sb = smem_u32(smg);

    const int tid = threadIdx.x;
    const int lid = tid & 31;
    const int wid = tid >> 5;
    const int wm = wid & 3;
    const int wn = wid >> 2;
    const int m0 = blockIdx.y << 7;
    const int n0 = blockIdx.x << 7;

    float acc[2][8][4];
#pragma unroll
    for (int i = 0; i < 2; i++)
#pragma unroll
        for (int j = 0; j < 8; j++)
#pragma unroll
            for (int v = 0; v < 4; v++) acc[i][j][v] = 0.f;

    const int nchunks = K >> 5;
    gemm_cp(sb, Ah, Al, Bh, Bl, m0, n0, 0, K, tid);
    CP_COMMIT();

#pragma unroll 1
    for (int t = 0; t < nchunks; ++t) {
        if (t + 1 < nchunks) {
            gemm_cp(sb + ((t + 1) & 1) * GSTAGE, Ah, Al, Bh, Bl,
                    m0, n0, (t + 1) << 5, K, tid);
            CP_COMMIT();
            CP_WAIT1();
        } else {
            CP_WAIT0();
        }
        __syncthreads();

        const uint32_t st = sb + (t & 1) * GSTAGE;
#pragma unroll
        for (int ks = 0; ks < 2; ks++) {
            uint32_t ah[2][4], al[2][4], bh[8][2], bl[8][2];
#pragma unroll
            for (int i = 0; i < 2; i++) {
                int r = wm * 32 + i * 16 + (lid & 15);
                int c = ks * 16 + (lid >> 4) * 8;
                uint32_t off = (uint32_t)(r * GST + c) * 2;
                ldsm4(ah[i], st + off);
                ldsm4(al[i], st + GBUF + off);
            }
#pragma unroll
            for (int jp = 0; jp < 4; jp++) {
                int r = wn * 64 + (2 * jp + ((lid >> 4) & 1)) * 8 + (lid & 7);
                int c = ks * 16 + ((lid >> 3) & 1) * 8;
                uint32_t off = (uint32_t)(r * GST + c) * 2;
                uint32_t b4h[4], b4l[4];
                ldsm4(b4h, st + 2 * GBUF + off);
                ldsm4(b4l, st + 3 * GBUF + off);
                bh[2 * jp][0] = b4h[0]; bh[2 * jp][1] = b4h[1];
                bh[2 * jp + 1][0] = b4h[2]; bh[2 * jp + 1][1] = b4h[3];
                bl[2 * jp][0] = b4l[0]; bl[2 * jp][1] = b4l[1];
                bl[2 * jp + 1][0] = b4l[2]; bl[2 * jp + 1][1] = b4l[3];
            }
#pragma unroll
            for (int i = 0; i < 2; i++)
#pragma unroll
                for (int j = 0; j < 8; j++) {
                    mma_bf16(acc[i][j], ah[i], bh[j]);
                    mma_bf16(acc[i][j], ah[i], bl[j]);
                    mma_bf16(acc[i][j], al[i], bh[j]);
                }
        }
        __syncthreads();
    }

    // epilogue
    const int qr = lid >> 2, qc = (lid & 3) << 1;
#pragma unroll
    for (int i = 0; i < 2; i++) {
#pragma unroll
        for (int j = 0; j < 8; j++) {
            int r0 = m0 + wm * 32 + i * 16 + qr;
            int c  = n0 + wn * 64 + j * 8 + qc;
#pragma unroll
            for (int hh = 0; hh < 2; hh++) {
                int m = r0 + hh * 8;
                float v0 = acc[i][j][2 * hh], v1 = acc[i][j][2 * hh + 1];
                if (MODE == 0) {
                    int bb = m >> 11, n = m & (SEQ - 1);
                    int which = c >> 10, cc = c & 1023;
                    int hd = cc >> 6, d = cc & 63;
                    size_t idx = ((size_t)(bb * NH + hd) * SEQ + n) * HD + d;
                    if (which == 0) { v0 *= QSCALE; v1 *= QSCALE; }
                    float h0 = bhi(v0), h1 = bhi(v1);
                    uint32_t uh = pack2(h0, h1);
                    uint32_t ul = pack2(v0 - h0, v1 - h1);
                    __nv_bfloat16* ph = (which == 0) ? g_Qh : (which == 1) ? g_Kh : g_Vh;
                    __nv_bfloat16* pl = (which == 0) ? g_Ql : (which == 1) ? g_Kl : g_Vl;
                    *reinterpret_cast<uint32_t*>(ph + idx) = uh;
                    *reinterpret_cast<uint32_t*>(pl + idx) = ul;
                } else {
                    float2 bv = *reinterpret_cast<const float2*>(bias + c);
                    float2 v = { v0 + bv.x, v1 + bv.y };
                    *reinterpret_cast<float2*>(Cout + (size_t)m * N + c) = v;
                }
            }
        }
    }
}

// ===========================================================================
// bf16x3 flash attention on pre-split Q/K/V.
// CTA: 128 q-rows, 8 warps (16 q-rows each), 64-row KV tiles, cp.async
// double-buffered. Epilogue writes AO as bf16 hi/lo for the proj GEMM.
// ===========================================================================
#define AST       72                       // smem row stride (bf16): 144B
#define ABUF      (64 * AST * 2)           // 9216 B per operand buffer
#define ASTAGE    (4 * ABUF)               // 36864 B per stage
#define SMEM_ATTN (2 * ASTAGE)             // 73728 B

__device__ __forceinline__ void attn_cp_kv(
    uint32_t stage, const __nv_bfloat16* Kh, const __nv_bfloat16* Kl,
    const __nv_bfloat16* Vh, const __nv_bfloat16* Vl, int kt, int tid)
{
#pragma unroll
    for (int it = 0; it < 8; it++) {
        int slot = tid + (it << 8);          // 0..2047
        int buf  = slot >> 9;                // 0:Kh 1:Kl 2:Vh 3:Vl
        int s2   = slot & 511;
        int r    = s2 >> 3;                  // 0..63
        int c16  = s2 & 7;                   // 0..7
        const __nv_bfloat16* base = (buf == 0) ? Kh : (buf == 1) ? Kl
                                  : (buf == 2) ? Vh : Vl;
        cp16(stage + buf * ABUF + r * (AST * 2) + c16 * 16,
             base + (size_t)(kt * 64 + r) * HD + c16 * 8);
    }
}

__global__ __launch_bounds__(256) void attn_mma()
{
    extern __shared__ __align__(16) char sma[];
    const uint32_t sb = smem_u32(sma);

    const int tid = threadIdx.x;
    const int lid = tid & 31;
    const int w   = tid >> 5;
    const int bh  = blockIdx.y;
    const int q0  = blockIdx.x << 7;

    const size_t hoff = (size_t)bh * SEQ * HD;
    const __nv_bfloat16* Qhp = g_Qh + hoff;
    const __nv_bfloat16* Qlp = g_Ql + hoff;
    const __nv_bfloat16* Khp = g_Kh + hoff;
    const __nv_bfloat16* Klp = g_Kl + hoff;
    const __nv_bfloat16* Vhp = g_Vh + hoff;
    const __nv_bfloat16* Vlp = g_Vl + hoff;

    // ---- stage Q (128 x 64 bf16, hi+lo) via cp.async into stage 0 area ----
#pragma unroll
    for (int it = 0; it < 8; it++) {
        int slot = tid + (it << 8);          // 0..2047
        int half = slot >> 10;               // 0:h 1:l
        int s2   = slot & 1023;
        int r    = s2 >> 3;                  // 0..127
        int c16  = s2 & 7;
        const __nv_bfloat16* base = half ? Qlp : Qhp;
        cp16(sb + half * (128 * AST * 2) + r * (AST * 2) + c16 * 16,
             base + (size_t)(q0 + r) * HD + c16 * 8);
    }
    CP_COMMIT();
    CP_WAIT0();
    __syncthreads();

    uint32_t qh[4][4], ql[4][4];
#pragma unroll
    for (int k4 = 0; k4 < 4; k4++) {
        int r = w * 16 + (lid & 15);
        int c = k4 * 16 + (lid >> 4) * 8;
        uint32_t off = (uint32_t)(r * AST + c) * 2;
        ldsm4(qh[k4], sb + off);
        ldsm4(ql[k4], sb + 128 * AST * 2 + off);
    }
    __syncthreads();      // Q staging free; begin KV pipeline

    float o[8][4];
#pragma unroll
    for (int j = 0; j < 8; j++)
#pragma unroll
        for (int v = 0; v < 4; v++) o[j][v] = 0.f;
    float mrow[2] = { -1e30f, -1e30f };
    float lrow[2] = { 0.f, 0.f };

    attn_cp_kv(sb, Khp, Klp, Vhp, Vlp, 0, tid);
    CP_COMMIT();

#pragma unroll 1
    for (int kt = 0; kt < SEQ / 64; kt++) {
        if (kt + 1 < SEQ / 64) {
            attn_cp_kv(sb + ((kt + 1) & 1) * ASTAGE, Khp, Klp, Vhp, Vlp, kt + 1, tid);
            CP_COMMIT();
            CP_WAIT1();
        } else {
            CP_WAIT0();
        }
        __syncthreads();
        const uint32_t st = sb + (kt & 1) * ASTAGE;

        // ---- S = Q @ K^T ----
        float s[8][4];
#pragma unroll
        for (int j = 0; j < 8; j++)
#pragma unroll
            for (int v = 0; v < 4; v++) s[j][v] = 0.f;
#pragma unroll
        for (int k4 = 0; k4 < 4; k4++) {
#pragma unroll
            for (int jp = 0; jp < 4; jp++) {
                int r = (2 * jp + ((lid >> 4) & 1)) * 8 + (lid & 7);
                int c = k4 * 16 + ((lid >> 3) & 1) * 8;
                uint32_t off = (uint32_t)(r * AST + c) * 2;
                uint32_t kh4[4], kl4[4];
                ldsm4(kh4, st + off);
                ldsm4(kl4, st + ABUF + off);
                mma_bf16(s[2 * jp],     qh[k4], kh4);
                mma_bf16(s[2 * jp],     qh[k4], kl4);
                mma_bf16(s[2 * jp],     ql[k4], kh4);
                mma_bf16(s[2 * jp + 1], qh[k4], kh4 + 2);
                mma_bf16(s[2 * jp + 1], qh[k4], kl4 + 2);
                mma_bf16(s[2 * jp + 1], ql[k4], kh4 + 2);
            }
        }

        // ---- online softmax (row halves qr and qr+8) ----
#pragma unroll
        for (int hh = 0; hh < 2; hh++) {
            float rm = -1e30f;
#pragma unroll
            for (int j = 0; j < 8; j++)
                rm = fmaxf(rm, fmaxf(s[j][2 * hh], s[j][2 * hh + 1]));
            rm = fmaxf(rm, __shfl_xor_sync(0xffffffffu, rm, 1));
            rm = fmaxf(rm, __shfl_xor_sync(0xffffffffu, rm, 2));
            float mnew = fmaxf(mrow[hh], rm);
            float corr = __expf(mrow[hh] - mnew);
            mrow[hh] = mnew;
            float ls = lrow[hh] * corr;
#pragma unroll
            for (int j = 0; j < 8; j++) {
                float p0 = __expf(s[j][2 * hh]     - mnew);
                float p1 = __expf(s[j][2 * hh + 1] - mnew);
                s[j][2 * hh] = p0; s[j][2 * hh + 1] = p1;
                ls += p0 + p1;
                o[j][2 * hh]     *= corr;
                o[j][2 * hh + 1] *= corr;
            }
            lrow[hh] = ls;
        }

        // ---- repack P into A-frags (hi/lo) ----
        uint32_t ph[4][4], pl[4][4];
#pragma unroll
        for (int t = 0; t < 4; t++) {
#pragma unroll
            for (int half = 0; half < 2; half++) {
                const float* sv = s[2 * t + half];
#pragma unroll
                for (int hh = 0; hh < 2; hh++) {
                    float p0 = sv[2 * hh], p1 = sv[2 * hh + 1];
                    float h0 = bhi(p0), h1 = bhi(p1);
                    ph[t][2 * half + hh] = pack2(h0, h1);
                    pl[t][2 * half + hh] = pack2(p0 - h0, p1 - h1);
                }
            }
        }

        // ---- O += P @ V ----
#pragma unroll
        for (int jp = 0; jp < 4; jp++) {
#pragma unroll
            for (int t = 0; t < 4; t++) {
                int r = t * 16 + (lid & 15);
                int c = (2 * jp + ((lid >> 4) & 1)) * 8;
                uint32_t off = (uint32_t)(r * AST + c) * 2;
                uint32_t vh4[4], vl4[4];
                ldsm4t(vh4, st + 2 * ABUF + off);
                ldsm4t(vl4, st + 3 * ABUF + off);
                mma_bf16(o[2 * jp],     ph[t], vh4);
                mma_bf16(o[2 * jp],     ph[t], vl4);
                mma_bf16(o[2 * jp],     pl[t], vh4);
                mma_bf16(o[2 * jp + 1], ph[t], vh4 + 2);
                mma_bf16(o[2 * jp + 1], ph[t], vl4 + 2);
                mma_bf16(o[2 * jp + 1], pl[t], vh4 + 2);
            }
        }
        __syncthreads();
    }

    // ---- epilogue: normalize, split hi/lo, write g_AOh/g_AOl [B,N,C] ----
#pragma unroll
    for (int hh = 0; hh < 2; hh++) {
        lrow[hh] += __shfl_xor_sync(0xffffffffu, lrow[hh], 1);
        lrow[hh] += __shfl_xor_sync(0xffffffffu, lrow[hh], 2);
    }
    const int bb = bh >> 4, hd = bh & 15;
    const int qr = lid >> 2, qc = (lid & 3) << 1;
#pragma unroll
    for (int hh = 0; hh < 2; hh++) {
        float inv = 1.f / lrow[hh];
        int n = q0 + w * 16 + qr + hh * 8;
        size_t base = ((size_t)(bb * SEQ + n)) * DIMC + hd * HD;
#pragma unroll
        for (int j = 0; j < 8; j++) {
            float v0 = o[j][2 * hh] * inv, v1 = o[j][2 * hh + 1] * inv;
            float h0 = bhi(v0), h1 = bhi(v1);
            *reinterpret_cast<uint32_t*>(g_AOh + base + j * 8 + qc) = pack2(h0, h1);
            *reinterpret_cast<uint32_t*>(g_AOl + base + j * 8 + qc) = pack2(v0 - h0, v1 - h1);
        }
    }
}

// ---------------------------------------------------------------------------
extern "C" void kernel_launch(void* const* d_in, const int* in_sizes, int n_in,
                              void* d_out, int out_size)
{
    const float* x      = (const float*)d_in[0];
    const float* w_qkv  = (const float*)d_in[1];
    const float* w_proj = (const float*)d_in[2];
    const float* b_proj = (const float*)d_in[3];
    float* out = (float*)d_out;

    __nv_bfloat16 *pXh, *pXl, *pWqh, *pWql, *pWph, *pWpl, *pAOh, *pAOl;
    cudaGetSymbolAddress((void**)&pXh,  g_Xh);
    cudaGetSymbolAddress((void**)&pXl,  g_Xl);
    cudaGetSymbolAddress((void**)&pWqh, g_Wqh);
    cudaGetSymbolAddress((void**)&pWql, g_Wql);
    cudaGetSymbolAddress((void**)&pWph, g_Wph);
    cudaGetSymbolAddress((void**)&pWpl, g_Wpl);
    cudaGetSymbolAddress((void**)&pAOh, g_AOh);
    cudaGetSymbolAddress((void**)&pAOl, g_AOl);

    cudaFuncSetAttribute(gemm_mma<0>,
                         cudaFuncAttributeMaxDynamicSharedMemorySize, SMEM_GEMM);
    cudaFuncSetAttribute(gemm_mma<1>,
                         cudaFuncAttributeMaxDynamicSharedMemorySize, SMEM_GEMM);
    cudaFuncSetAttribute(attn_mma,
                         cudaFuncAttributeMaxDynamicSharedMemorySize, SMEM_ATTN);

    // pre-split fp32 -> bf16 hi/lo
    int n4x = TOK * DIMC / 4, n4q = NQKV * DIMC / 4, n4p = DIMC * DIMC / 4;
    split_kernel<<<(n4x + 255) / 256, 256>>>(x, pXh, pXl, n4x);
    split_kernel<<<(n4q + 255) / 256, 256>>>(w_qkv, pWqh, pWql, n4q);
    split_kernel<<<(n4p + 255) / 256, 256>>>(w_proj, pWph, pWpl, n4p);

    dim3 g1(NQKV / 128, TOK / 128);      // (24, 64)
    gemm_mma<0><<<g1, 256, SMEM_GEMM>>>(pXh, pXl, pWqh, pWql,
                                        nullptr, nullptr, TOK, NQKV, DIMC);

    dim3 ga(SEQ / 128, BH);              // (16, 64)
    attn_mma<<<ga, 256, SMEM_ATTN>>>();

    dim3 g2(DIMC / 128, TOK / 128);      // (8, 64)
    gemm_mma<1><<<g2, 256, SMEM_GEMM>>>(pAOh, pAOl, pWph, pWpl,
                                        b_proj, out, TOK, DIMC, DIMC);
}

// round 13
// speedup vs baseline: 2.9711x; 1.0628x over previous
#include <cuda_runtime.h>
#include <cuda_bf16.h>
#include <cstdint>
#include <math.h>

// Problem constants
#define SEQ    2048
#define DIMC   1024
#define NH     16
#define HD     64
#define BATCH  4
#define BH     64          // BATCH*NH
#define TOK    8192        // BATCH*SEQ
#define NQKV   3072
#define QSCALE 0.125f      // 64^-0.5

// Persistent bf16 hi/lo scratch (allocation-free: __device__ globals)
__device__ __nv_bfloat16 g_Xh[(size_t)TOK * DIMC],  g_Xl[(size_t)TOK * DIMC];
__device__ __nv_bfloat16 g_Wqh[(size_t)NQKV * DIMC], g_Wql[(size_t)NQKV * DIMC];
__device__ __nv_bfloat16 g_Wph[(size_t)DIMC * DIMC], g_Wpl[(size_t)DIMC * DIMC];
__device__ __nv_bfloat16 g_Qh[(size_t)BH * SEQ * HD], g_Ql[(size_t)BH * SEQ * HD];
__device__ __nv_bfloat16 g_Kh[(size_t)BH * SEQ * HD], g_Kl[(size_t)BH * SEQ * HD];
__device__ __nv_bfloat16 g_Vh[(size_t)BH * SEQ * HD], g_Vl[(size_t)BH * SEQ * HD];
__device__ __nv_bfloat16 g_AOh[(size_t)TOK * DIMC],  g_AOl[(size_t)TOK * DIMC];

// ===========================================================================
// helpers (legal on base sm_103 target: mma.sync / ldmatrix / cp.async)
// ===========================================================================
__device__ __forceinline__ uint32_t smem_u32(const void* p) {
    uint32_t a;
    asm("{ .reg .u64 t; cvta.to.shared.u64 t, %1; cvt.u32.u64 %0, t; }"
        : "=r"(a) : "l"(p));
    return a;
}
__device__ __forceinline__ void mma_bf16(float* c, const uint32_t* a, const uint32_t* b) {
    asm volatile(
        "mma.sync.aligned.m16n8k16.row.col.f32.bf16.bf16.f32 "
        "{%0,%1,%2,%3}, {%4,%5,%6,%7}, {%8,%9}, {%0,%1,%2,%3};"
        : "+f"(c[0]), "+f"(c[1]), "+f"(c[2]), "+f"(c[3])
        : "r"(a[0]), "r"(a[1]), "r"(a[2]), "r"(a[3]), "r"(b[0]), "r"(b[1]));
}
__device__ __forceinline__ void ldsm4(uint32_t* r, uint32_t addr) {
    asm volatile("ldmatrix.sync.aligned.m8n8.x4.shared.b16 {%0,%1,%2,%3}, [%4];"
                 : "=r"(r[0]), "=r"(r[1]), "=r"(r[2]), "=r"(r[3]) : "r"(addr));
}
__device__ __forceinline__ void ldsm4t(uint32_t* r, uint32_t addr) {
    asm volatile("ldmatrix.sync.aligned.m8n8.x4.trans.shared.b16 {%0,%1,%2,%3}, [%4];"
                 : "=r"(r[0]), "=r"(r[1]), "=r"(r[2]), "=r"(r[3]) : "r"(addr));
}
__device__ __forceinline__ void cp16(uint32_t dst, const void* src) {
    asm volatile("cp.async.cg.shared.global [%0], [%1], 16;" :: "r"(dst), "l"(src));
}
#define CP_COMMIT()  asm volatile("cp.async.commit_group;" ::: "memory")
#define CP_WAIT0()   asm volatile("cp.async.wait_group 0;" ::: "memory")
#define CP_WAIT1()   asm volatile("cp.async.wait_group 1;" ::: "memory")

// pack two fp32 -> bf16x2 reg (lo lane = first arg)
__device__ __forceinline__ uint32_t pack2(float lo, float hi) {
    uint32_t r;
    asm("cvt.rn.bf16x2.f32 %0, %1, %2;" : "=r"(r) : "f"(hi), "f"(lo));
    return r;
}
__device__ __forceinline__ float bhi(float v) {
    return __bfloat162float(__float2bfloat16(v));
}

// ===========================================================================
// split kernel: fp32 -> bf16 hi + bf16 lo (residual)
// ===========================================================================
__global__ __launch_bounds__(256) void split_kernel(
    const float* __restrict__ in, __nv_bfloat16* __restrict__ oh,
    __nv_bfloat16* __restrict__ ol, int n4)
{
    int i = blockIdx.x * blockDim.x + threadIdx.x;
    if (i >= n4) return;
    float4 v = reinterpret_cast<const float4*>(in)[i];
    float hx = bhi(v.x), hy = bhi(v.y), hz = bhi(v.z), hw = bhi(v.w);
    uint2 uh = { pack2(hx, hy), pack2(hz, hw) };
    uint2 ul = { pack2(v.x - hx, v.y - hy), pack2(v.z - hz, v.w - hw) };
    reinterpret_cast<uint2*>(oh)[i] = uh;
    reinterpret_cast<uint2*>(ol)[i] = ul;
}

// ===========================================================================
// bf16x3 GEMM on pre-split operands: C = A @ W^T, A[M,K], W[N,K] row-major.
// 128x128 CTA, 256 threads (8 warps: 4 along M x 2 along N), K chunks of 32,
// cp.async double-buffered smem. __launch_bounds__(256,2) caps regs at 128
// so 2 CTAs/SM co-reside; B-frags loaded per-jp and consumed immediately
// (8 live regs instead of 32) to stay spill-free under the cap.
// MODE 0: scatter hi/lo -> Q/K/V.  MODE 1: +bias -> fp32 Cout.
// ===========================================================================
#define GST       40                       // smem row stride (bf16): 80B
#define GBUF      (128 * GST * 2)          // 10240 B per operand buffer
#define GSTAGE    (4 * GBUF)               // 40960 B per stage
#define SMEM_GEMM (2 * GSTAGE)             // 81920 B

__device__ __forceinline__ void gemm_cp(
    uint32_t stage, const __nv_bfloat16* Ah, const __nv_bfloat16* Al,
    const __nv_bfloat16* Bh, const __nv_bfloat16* Bl,
    int m0, int n0, int k0, int K, int tid)
{
#pragma unroll
    for (int it = 0; it < 8; it++) {
        int slot = tid + (it << 8);          // 0..2047
        int buf  = slot >> 9;                // 0:Ah 1:Al 2:Bh 3:Bl
        int s2   = slot & 511;
        int r    = s2 >> 2;                  // 0..127
        int c16  = s2 & 3;                   // 0..3 (16B units)
        const __nv_bfloat16* base = (buf == 0) ? Ah : (buf == 1) ? Al
                                  : (buf == 2) ? Bh : Bl;
        int row = ((buf < 2) ? m0 : n0) + r;
        cp16(stage + buf * GBUF + r * (GST * 2) + c16 * 16,
             base + (size_t)row * K + k0 + c16 * 8);
    }
}

template <int MODE>
__global__ __launch_bounds__(256, 2) void gemm_mma(
    const __nv_bfloat16* __restrict__ Ah, const __nv_bfloat16* __restrict__ Al,
    const __nv_bfloat16* __restrict__ Bh, const __nv_bfloat16* __restrict__ Bl,
    const float* __restrict__ bias, float* __restrict__ Cout,
    int M, int N, int K)
{
    extern __shared__ __align__(16) char smg[];
    const uint32_t sb = smem_u32(smg);

    const int tid = threadIdx.x;
    const int lid = tid & 31;
    const int wid = tid >> 5;
    const int wm = wid & 3;
    const int wn = wid >> 2;
    const int m0 = blockIdx.y << 7;
    const int n0 = blockIdx.x << 7;

    float acc[2][8][4];
#pragma unroll
    for (int i = 0; i < 2; i++)
#pragma unroll
        for (int j = 0; j < 8; j++)
#pragma unroll
            for (int v = 0; v < 4; v++) acc[i][j][v] = 0.f;

    // precomputed intra-stage offsets (loop-invariant)
    const uint32_t aoffs[2] = {
        (uint32_t)((wm * 32 + (lid & 15)) * GST + (lid >> 4) * 8) * 2,
        (uint32_t)((wm * 32 + 16 + (lid & 15)) * GST + (lid >> 4) * 8) * 2 };
    uint32_t boffs[4];
#pragma unroll
    for (int jp = 0; jp < 4; jp++)
        boffs[jp] = (uint32_t)((wn * 64 + (2 * jp + ((lid >> 4) & 1)) * 8 + (lid & 7)) * GST
                               + ((lid >> 3) & 1) * 8) * 2;

    const int nchunks = K >> 5;
    gemm_cp(sb, Ah, Al, Bh, Bl, m0, n0, 0, K, tid);
    CP_COMMIT();

#pragma unroll 1
    for (int t = 0; t < nchunks; ++t) {
        if (t + 1 < nchunks) {
            gemm_cp(sb + ((t + 1) & 1) * GSTAGE, Ah, Al, Bh, Bl,
                    m0, n0, (t + 1) << 5, K, tid);
            CP_COMMIT();
            CP_WAIT1();
        } else {
            CP_WAIT0();
        }
        __syncthreads();

        const uint32_t st = sb + (t & 1) * GSTAGE;
#pragma unroll
        for (int ks = 0; ks < 2; ks++) {
            const uint32_t kso = (uint32_t)(ks * 16) * 2;
            uint32_t ah[2][4], al[2][4];
#pragma unroll
            for (int i = 0; i < 2; i++) {
                ldsm4(ah[i], st + aoffs[i] + kso);
                ldsm4(al[i], st + GBUF + aoffs[i] + kso);
            }
#pragma unroll
            for (int jp = 0; jp < 4; jp++) {
                uint32_t b4h[4], b4l[4];
                ldsm4(b4h, st + 2 * GBUF + boffs[jp] + kso);
                ldsm4(b4l, st + 3 * GBUF + boffs[jp] + kso);
#pragma unroll
                for (int i = 0; i < 2; i++) {
                    mma_bf16(acc[i][2 * jp],     ah[i], b4h);
                    mma_bf16(acc[i][2 * jp],     ah[i], b4l);
                    mma_bf16(acc[i][2 * jp],     al[i], b4h);
                    mma_bf16(acc[i][2 * jp + 1], ah[i], b4h + 2);
                    mma_bf16(acc[i][2 * jp + 1], ah[i], b4l + 2);
                    mma_bf16(acc[i][2 * jp + 1], al[i], b4h + 2);
                }
            }
        }
        __syncthreads();
    }

    // epilogue
    const int qr = lid >> 2, qc = (lid & 3) << 1;
#pragma unroll
    for (int i = 0; i < 2; i++) {
#pragma unroll
        for (int j = 0; j < 8; j++) {
            int r0 = m0 + wm * 32 + i * 16 + qr;
            int c  = n0 + wn * 64 + j * 8 + qc;
#pragma unroll
            for (int hh = 0; hh < 2; hh++) {
                int m = r0 + hh * 8;
                float v0 = acc[i][j][2 * hh], v1 = acc[i][j][2 * hh + 1];
                if (MODE == 0) {
                    int bb = m >> 11, n = m & (SEQ - 1);
                    int which = c >> 10, cc = c & 1023;
                    int hd = cc >> 6, d = cc & 63;
                    size_t idx = ((size_t)(bb * NH + hd) * SEQ + n) * HD + d;
                    if (which == 0) { v0 *= QSCALE; v1 *= QSCALE; }
                    float h0 = bhi(v0), h1 = bhi(v1);
                    uint32_t uh = pack2(h0, h1);
                    uint32_t ul = pack2(v0 - h0, v1 - h1);
                    __nv_bfloat16* ph = (which == 0) ? g_Qh : (which == 1) ? g_Kh : g_Vh;
                    __nv_bfloat16* pl = (which == 0) ? g_Ql : (which == 1) ? g_Kl : g_Vl;
                    *reinterpret_cast<uint32_t*>(ph + idx) = uh;
                    *reinterpret_cast<uint32_t*>(pl + idx) = ul;
                } else {
                    float2 bv = *reinterpret_cast<const float2*>(bias + c);
                    float2 v = { v0 + bv.x, v1 + bv.y };
                    *reinterpret_cast<float2*>(Cout + (size_t)m * N + c) = v;
                }
            }
        }
    }
}

// ===========================================================================
// bf16x3 flash attention on pre-split Q/K/V (unchanged from R9).
// ===========================================================================
#define AST       72                       // smem row stride (bf16): 144B
#define ABUF      (64 * AST * 2)           // 9216 B per operand buffer
#define ASTAGE    (4 * ABUF)               // 36864 B per stage
#define SMEM_ATTN (2 * ASTAGE)             // 73728 B

__device__ __forceinline__ void attn_cp_kv(
    uint32_t stage, const __nv_bfloat16* Kh, const __nv_bfloat16* Kl,
    const __nv_bfloat16* Vh, const __nv_bfloat16* Vl, int kt, int tid)
{
#pragma unroll
    for (int it = 0; it < 8; it++) {
        int slot = tid + (it << 8);          // 0..2047
        int buf  = slot >> 9;                // 0:Kh 1:Kl 2:Vh 3:Vl
        int s2   = slot & 511;
        int r    = s2 >> 3;                  // 0..63
        int c16  = s2 & 7;                   // 0..7
        const __nv_bfloat16* base = (buf == 0) ? Kh : (buf == 1) ? Kl
                                  : (buf == 2) ? Vh : Vl;
        cp16(stage + buf * ABUF + r * (AST * 2) + c16 * 16,
             base + (size_t)(kt * 64 + r) * HD + c16 * 8);
    }
}

__global__ __launch_bounds__(256) void attn_mma()
{
    extern __shared__ __align__(16) char sma[];
    const uint32_t sb = smem_u32(sma);

    const int tid = threadIdx.x;
    const int lid = tid & 31;
    const int w   = tid >> 5;
    const int bh  = blockIdx.y;
    const int q0  = blockIdx.x << 7;

    const size_t hoff = (size_t)bh * SEQ * HD;
    const __nv_bfloat16* Qhp = g_Qh + hoff;
    const __nv_bfloat16* Qlp = g_Ql + hoff;
    const __nv_bfloat16* Khp = g_Kh + hoff;
    const __nv_bfloat16* Klp = g_Kl + hoff;
    const __nv_bfloat16* Vhp = g_Vh + hoff;
    const __nv_bfloat16* Vlp = g_Vl + hoff;

    // ---- stage Q (128 x 64 bf16, hi+lo) via cp.async into stage 0 area ----
#pragma unroll
    for (int it = 0; it < 8; it++) {
        int slot = tid + (it << 8);          // 0..2047
        int half = slot >> 10;               // 0:h 1:l
        int s2   = slot & 1023;
        int r    = s2 >> 3;                  // 0..127
        int c16  = s2 & 7;
        const __nv_bfloat16* base = half ? Qlp : Qhp;
        cp16(sb + half * (128 * AST * 2) + r * (AST * 2) + c16 * 16,
             base + (size_t)(q0 + r) * HD + c16 * 8);
    }
    CP_COMMIT();
    CP_WAIT0();
    __syncthreads();

    uint32_t qh[4][4], ql[4][4];
#pragma unroll
    for (int k4 = 0; k4 < 4; k4++) {
        int r = w * 16 + (lid & 15);
        int c = k4 * 16 + (lid >> 4) * 8;
        uint32_t off = (uint32_t)(r * AST + c) * 2;
        ldsm4(qh[k4], sb + off);
        ldsm4(ql[k4], sb + 128 * AST * 2 + off);
    }
    __syncthreads();      // Q staging free; begin KV pipeline

    float o[8][4];
#pragma unroll
    for (int j = 0; j < 8; j++)
#pragma unroll
        for (int v = 0; v < 4; v++) o[j][v] = 0.f;
    float mrow[2] = { -1e30f, -1e30f };
    float lrow[2] = { 0.f, 0.f };

    attn_cp_kv(sb, Khp, Klp, Vhp, Vlp, 0, tid);
    CP_COMMIT();

#pragma unroll 1
    for (int kt = 0; kt < SEQ / 64; kt++) {
        if (kt + 1 < SEQ / 64) {
            attn_cp_kv(sb + ((kt + 1) & 1) * ASTAGE, Khp, Klp, Vhp, Vlp, kt + 1, tid);
            CP_COMMIT();
            CP_WAIT1();
        } else {
            CP_WAIT0();
        }
        __syncthreads();
        const uint32_t st = sb + (kt & 1) * ASTAGE;

        // ---- S = Q @ K^T ----
        float s[8][4];
#pragma unroll
        for (int j = 0; j < 8; j++)
#pragma unroll
            for (int v = 0; v < 4; v++) s[j][v] = 0.f;
#pragma unroll
        for (int k4 = 0; k4 < 4; k4++) {
#pragma unroll
            for (int jp = 0; jp < 4; jp++) {
                int r = (2 * jp + ((lid >> 4) & 1)) * 8 + (lid & 7);
                int c = k4 * 16 + ((lid >> 3) & 1) * 8;
                uint32_t off = (uint32_t)(r * AST + c) * 2;
                uint32_t kh4[4], kl4[4];
                ldsm4(kh4, st + off);
                ldsm4(kl4, st + ABUF + off);
                mma_bf16(s[2 * jp],     qh[k4], kh4);
                mma_bf16(s[2 * jp],     qh[k4], kl4);
                mma_bf16(s[2 * jp],     ql[k4], kh4);
                mma_bf16(s[2 * jp + 1], qh[k4], kh4 + 2);
                mma_bf16(s[2 * jp + 1], qh[k4], kl4 + 2);
                mma_bf16(s[2 * jp + 1], ql[k4], kh4 + 2);
            }
        }

        // ---- online softmax (row halves qr and qr+8) ----
#pragma unroll
        for (int hh = 0; hh < 2; hh++) {
            float rm = -1e30f;
#pragma unroll
            for (int j = 0; j < 8; j++)
                rm = fmaxf(rm, fmaxf(s[j][2 * hh], s[j][2 * hh + 1]));
            rm = fmaxf(rm, __shfl_xor_sync(0xffffffffu, rm, 1));
            rm = fmaxf(rm, __shfl_xor_sync(0xffffffffu, rm, 2));
            float mnew = fmaxf(mrow[hh], rm);
            float corr = __expf(mrow[hh] - mnew);
            mrow[hh] = mnew;
            float ls = lrow[hh] * corr;
#pragma unroll
            for (int j = 0; j < 8; j++) {
                float p0 = __expf(s[j][2 * hh]     - mnew);
                float p1 = __expf(s[j][2 * hh + 1] - mnew);
                s[j][2 * hh] = p0; s[j][2 * hh + 1] = p1;
                ls += p0 + p1;
                o[j][2 * hh]     *= corr;
                o[j][2 * hh + 1] *= corr;
            }
            lrow[hh] = ls;
        }

        // ---- repack P into A-frags (hi/lo) ----
        uint32_t ph[4][4], pl[4][4];
#pragma unroll
        for (int t = 0; t < 4; t++) {
#pragma unroll
            for (int half = 0; half < 2; half++) {
                const float* sv = s[2 * t + half];
#pragma unroll
                for (int hh = 0; hh < 2; hh++) {
                    float p0 = sv[2 * hh], p1 = sv[2 * hh + 1];
                    float h0 = bhi(p0), h1 = bhi(p1);
                    ph[t][2 * half + hh] = pack2(h0, h1);
                    pl[t][2 * half + hh] = pack2(p0 - h0, p1 - h1);
                }
            }
        }

        // ---- O += P @ V ----
#pragma unroll
        for (int jp = 0; jp < 4; jp++) {
#pragma unroll
            for (int t = 0; t < 4; t++) {
                int r = t * 16 + (lid & 15);
                int c = (2 * jp + ((lid >> 4) & 1)) * 8;
                uint32_t off = (uint32_t)(r * AST + c) * 2;
                uint32_t vh4[4], vl4[4];
                ldsm4t(vh4, st + 2 * ABUF + off);
                ldsm4t(vl4, st + 3 * ABUF + off);
                mma_bf16(o[2 * jp],     ph[t], vh4);
                mma_bf16(o[2 * jp],     ph[t], vl4);
                mma_bf16(o[2 * jp],     pl[t], vh4);
                mma_bf16(o[2 * jp + 1], ph[t], vh4 + 2);
                mma_bf16(o[2 * jp + 1], ph[t], vl4 + 2);
                mma_bf16(o[2 * jp + 1], pl[t], vh4 + 2);
            }
        }
        __syncthreads();
    }

    // ---- epilogue: normalize, split hi/lo, write g_AOh/g_AOl [B,N,C] ----
#pragma unroll
    for (int hh = 0; hh < 2; hh++) {
        lrow[hh] += __shfl_xor_sync(0xffffffffu, lrow[hh], 1);
        lrow[hh] += __shfl_xor_sync(0xffffffffu, lrow[hh], 2);
    }
    const int bb = bh >> 4, hd = bh & 15;
    const int qr = lid >> 2, qc = (lid & 3) << 1;
#pragma unroll
    for (int hh = 0; hh < 2; hh++) {
        float inv = 1.f / lrow[hh];
        int n = q0 + w * 16 + qr + hh * 8;
        size_t base = ((size_t)(bb * SEQ + n)) * DIMC + hd * HD;
#pragma unroll
        for (int j = 0; j < 8; j++) {
            float v0 = o[j][2 * hh] * inv, v1 = o[j][2 * hh + 1] * inv;
            float h0 = bhi(v0), h1 = bhi(v1);
            *reinterpret_cast<uint32_t*>(g_AOh + base + j * 8 + qc) = pack2(h0, h1);
            *reinterpret_cast<uint32_t*>(g_AOl + base + j * 8 + qc) = pack2(v0 - h0, v1 - h1);
        }
    }
}

// ---------------------------------------------------------------------------
extern "C" void kernel_launch(void* const* d_in, const int* in_sizes, int n_in,
                              void* d_out, int out_size)
{
    const float* x      = (const float*)d_in[0];
    const float* w_qkv  = (const float*)d_in[1];
    const float* w_proj = (const float*)d_in[2];
    const float* b_proj = (const float*)d_in[3];
    float* out = (float*)d_out;

    __nv_bfloat16 *pXh, *pXl, *pWqh, *pWql, *pWph, *pWpl, *pAOh, *pAOl;
    cudaGetSymbolAddress((void**)&pXh,  g_Xh);
    cudaGetSymbolAddress((void**)&pXl,  g_Xl);
    cudaGetSymbolAddress((void**)&pWqh, g_Wqh);
    cudaGetSymbolAddress((void**)&pWql, g_Wql);
    cudaGetSymbolAddress((void**)&pWph, g_Wph);
    cudaGetSymbolAddress((void**)&pWpl, g_Wpl);
    cudaGetSymbolAddress((void**)&pAOh, g_AOh);
    cudaGetSymbolAddress((void**)&pAOl, g_AOl);

    cudaFuncSetAttribute(gemm_mma<0>,
                         cudaFuncAttributeMaxDynamicSharedMemorySize, SMEM_GEMM);
    cudaFuncSetAttribute(gemm_mma<1>,
                         cudaFuncAttributeMaxDynamicSharedMemorySize, SMEM_GEMM);
    cudaFuncSetAttribute(attn_mma,
                         cudaFuncAttributeMaxDynamicSharedMemorySize, SMEM_ATTN);

    // pre-split fp32 -> bf16 hi/lo
    int n4x = TOK * DIMC / 4, n4q = NQKV * DIMC / 4, n4p = DIMC * DIMC / 4;
    split_kernel<<<(n4x + 255) / 256, 256>>>(x, pXh, pXl, n4x);
    split_kernel<<<(n4q + 255) / 256, 256>>>(w_qkv, pWqh, pWql, n4q);
    split_kernel<<<(n4p + 255) / 256, 256>>>(w_proj, pWph, pWpl, n4p);

    dim3 g1(NQKV / 128, TOK / 128);      // (24, 64)
    gemm_mma<0><<<g1, 256, SMEM_GEMM>>>(pXh, pXl, pWqh, pWql,
                                        nullptr, nullptr, TOK, NQKV, DIMC);

    dim3 ga(SEQ / 128, BH);              // (16, 64)
    attn_mma<<<ga, 256, SMEM_ATTN>>>();

    dim3 g2(DIMC / 128, TOK / 128);      // (8, 64)
    gemm_mma<1><<<g2, 256, SMEM_GEMM>>>(pAOh, pAOl, pWph, pWpl,
                                        b_proj, out, TOK, DIMC, DIMC);
}

// round 14
// speedup vs baseline: 3.2800x; 1.1040x over previous
#include <cuda_runtime.h>
#include <cuda_bf16.h>
#include <cstdint>
#include <math.h>

// Problem constants
#define SEQ    2048
#define DIMC   1024
#define NH     16
#define HD     64
#define BATCH  4
#define BH     64          // BATCH*NH
#define TOK    8192        // BATCH*SEQ
#define NQKV   3072
#define QSCALE 0.125f      // 64^-0.5

// Persistent bf16 hi/lo scratch (allocation-free: __device__ globals)
__device__ __nv_bfloat16 g_Xh[(size_t)TOK * DIMC],  g_Xl[(size_t)TOK * DIMC];
__device__ __nv_bfloat16 g_Wqh[(size_t)NQKV * DIMC], g_Wql[(size_t)NQKV * DIMC];
__device__ __nv_bfloat16 g_Wph[(size_t)DIMC * DIMC], g_Wpl[(size_t)DIMC * DIMC];
__device__ __nv_bfloat16 g_Qh[(size_t)BH * SEQ * HD], g_Ql[(size_t)BH * SEQ * HD];
__device__ __nv_bfloat16 g_Kh[(size_t)BH * SEQ * HD], g_Kl[(size_t)BH * SEQ * HD];
__device__ __nv_bfloat16 g_Vh[(size_t)BH * SEQ * HD], g_Vl[(size_t)BH * SEQ * HD];
__device__ __nv_bfloat16 g_AOh[(size_t)TOK * DIMC],  g_AOl[(size_t)TOK * DIMC];

// ===========================================================================
// helpers (legal on base sm_103 target: mma.sync / ldmatrix / cp.async)
// ===========================================================================
__device__ __forceinline__ uint32_t smem_u32(const void* p) {
    uint32_t a;
    asm("{ .reg .u64 t; cvta.to.shared.u64 t, %1; cvt.u32.u64 %0, t; }"
        : "=r"(a) : "l"(p));
    return a;
}
__device__ __forceinline__ void mma_bf16(float* c, const uint32_t* a, const uint32_t* b) {
    asm volatile(
        "mma.sync.aligned.m16n8k16.row.col.f32.bf16.bf16.f32 "
        "{%0,%1,%2,%3}, {%4,%5,%6,%7}, {%8,%9}, {%0,%1,%2,%3};"
        : "+f"(c[0]), "+f"(c[1]), "+f"(c[2]), "+f"(c[3])
        : "r"(a[0]), "r"(a[1]), "r"(a[2]), "r"(a[3]), "r"(b[0]), "r"(b[1]));
}
__device__ __forceinline__ void ldsm4(uint32_t* r, uint32_t addr) {
    asm volatile("ldmatrix.sync.aligned.m8n8.x4.shared.b16 {%0,%1,%2,%3}, [%4];"
                 : "=r"(r[0]), "=r"(r[1]), "=r"(r[2]), "=r"(r[3]) : "r"(addr));
}
__device__ __forceinline__ void ldsm4t(uint32_t* r, uint32_t addr) {
    asm volatile("ldmatrix.sync.aligned.m8n8.x4.trans.shared.b16 {%0,%1,%2,%3}, [%4];"
                 : "=r"(r[0]), "=r"(r[1]), "=r"(r[2]), "=r"(r[3]) : "r"(addr));
}
__device__ __forceinline__ void cp16(uint32_t dst, const void* src) {
    asm volatile("cp.async.cg.shared.global [%0], [%1], 16;" :: "r"(dst), "l"(src));
}
#define CP_COMMIT()  asm volatile("cp.async.commit_group;" ::: "memory")
#define CP_WAIT0()   asm volatile("cp.async.wait_group 0;" ::: "memory")
#define CP_WAIT1()   asm volatile("cp.async.wait_group 1;" ::: "memory")

// pack two fp32 -> bf16x2 reg (lo lane = first arg)
__device__ __forceinline__ uint32_t pack2(float lo, float hi) {
    uint32_t r;
    asm("cvt.rn.bf16x2.f32 %0, %1, %2;" : "=r"(r) : "f"(hi), "f"(lo));
    return r;
}
__device__ __forceinline__ float bhi(float v) {
    return __bfloat162float(__float2bfloat16(v));
}

// ===========================================================================
// split kernel: fp32 -> bf16 hi + bf16 lo (residual)
// ===========================================================================
__global__ __launch_bounds__(256) void split_kernel(
    const float* __restrict__ in, __nv_bfloat16* __restrict__ oh,
    __nv_bfloat16* __restrict__ ol, int n4)
{
    int i = blockIdx.x * blockDim.x + threadIdx.x;
    if (i >= n4) return;
    float4 v = reinterpret_cast<const float4*>(in)[i];
    float hx = bhi(v.x), hy = bhi(v.y), hz = bhi(v.z), hw = bhi(v.w);
    uint2 uh = { pack2(hx, hy), pack2(hz, hw) };
    uint2 ul = { pack2(v.x - hx, v.y - hy), pack2(v.z - hz, v.w - hw) };
    reinterpret_cast<uint2*>(oh)[i] = uh;
    reinterpret_cast<uint2*>(ol)[i] = ul;
}

// ===========================================================================
// bf16x3 GEMM, 128x128 CTA, 2 CTAs/SM, cp.async double buffer.
// MMA order interleaved across accumulators (chain distance 4).
// ===========================================================================
#define GST       40                       // smem row stride (bf16): 80B
#define GBUF      (128 * GST * 2)          // 10240 B per operand buffer
#define GSTAGE    (4 * GBUF)               // 40960 B per stage
#define SMEM_GEMM (2 * GSTAGE)             // 81920 B

__device__ __forceinline__ void gemm_cp(
    uint32_t stage, const __nv_bfloat16* Ah, const __nv_bfloat16* Al,
    const __nv_bfloat16* Bh, const __nv_bfloat16* Bl,
    int m0, int n0, int k0, int K, int tid)
{
#pragma unroll
    for (int it = 0; it < 8; it++) {
        int slot = tid + (it << 8);          // 0..2047
        int buf  = slot >> 9;                // 0:Ah 1:Al 2:Bh 3:Bl
        int s2   = slot & 511;
        int r    = s2 >> 2;                  // 0..127
        int c16  = s2 & 3;                   // 0..3 (16B units)
        const __nv_bfloat16* base = (buf == 0) ? Ah : (buf == 1) ? Al
                                  : (buf == 2) ? Bh : Bl;
        int row = ((buf < 2) ? m0 : n0) + r;
        cp16(stage + buf * GBUF + r * (GST * 2) + c16 * 16,
             base + (size_t)row * K + k0 + c16 * 8);
    }
}

template <int MODE>
__global__ __launch_bounds__(256, 2) void gemm_mma(
    const __nv_bfloat16* __restrict__ Ah, const __nv_bfloat16* __restrict__ Al,
    const __nv_bfloat16* __restrict__ Bh, const __nv_bfloat16* __restrict__ Bl,
    const float* __restrict__ bias, float* __restrict__ Cout,
    int M, int N, int K)
{
    extern __shared__ __align__(16) char smg[];
    const uint32_t sb = smem_u32(smg);

    const int tid = threadIdx.x;
    const int lid = tid & 31;
    const int wid = tid >> 5;
    const int wm = wid & 3;
    const int wn = wid >> 2;
    const int m0 = blockIdx.y << 7;
    const int n0 = blockIdx.x << 7;

    float acc[2][8][4];
#pragma unroll
    for (int i = 0; i < 2; i++)
#pragma unroll
        for (int j = 0; j < 8; j++)
#pragma unroll
            for (int v = 0; v < 4; v++) acc[i][j][v] = 0.f;

    const uint32_t aoffs[2] = {
        (uint32_t)((wm * 32 + (lid & 15)) * GST + (lid >> 4) * 8) * 2,
        (uint32_t)((wm * 32 + 16 + (lid & 15)) * GST + (lid >> 4) * 8) * 2 };
    uint32_t boffs[4];
#pragma unroll
    for (int jp = 0; jp < 4; jp++)
        boffs[jp] = (uint32_t)((wn * 64 + (2 * jp + ((lid >> 4) & 1)) * 8 + (lid & 7)) * GST
                               + ((lid >> 3) & 1) * 8) * 2;

    const int nchunks = K >> 5;
    gemm_cp(sb, Ah, Al, Bh, Bl, m0, n0, 0, K, tid);
    CP_COMMIT();

#pragma unroll 1
    for (int t = 0; t < nchunks; ++t) {
        if (t + 1 < nchunks) {
            gemm_cp(sb + ((t + 1) & 1) * GSTAGE, Ah, Al, Bh, Bl,
                    m0, n0, (t + 1) << 5, K, tid);
            CP_COMMIT();
            CP_WAIT1();
        } else {
            CP_WAIT0();
        }
        __syncthreads();

        const uint32_t st = sb + (t & 1) * GSTAGE;
#pragma unroll
        for (int ks = 0; ks < 2; ks++) {
            const uint32_t kso = (uint32_t)(ks * 16) * 2;
            uint32_t ah[2][4], al[2][4];
#pragma unroll
            for (int i = 0; i < 2; i++) {
                ldsm4(ah[i], st + aoffs[i] + kso);
                ldsm4(al[i], st + GBUF + aoffs[i] + kso);
            }
#pragma unroll
            for (int jp = 0; jp < 4; jp++) {
                uint32_t b4h[4], b4l[4];
                ldsm4(b4h, st + 2 * GBUF + boffs[jp] + kso);
                ldsm4(b4l, st + 3 * GBUF + boffs[jp] + kso);
                // interleaved: consecutive mmas hit different accumulators
                mma_bf16(acc[0][2 * jp],     ah[0], b4h);
                mma_bf16(acc[1][2 * jp],     ah[1], b4h);
                mma_bf16(acc[0][2 * jp + 1], ah[0], b4h + 2);
                mma_bf16(acc[1][2 * jp + 1], ah[1], b4h + 2);
                mma_bf16(acc[0][2 * jp],     ah[0], b4l);
                mma_bf16(acc[1][2 * jp],     ah[1], b4l);
                mma_bf16(acc[0][2 * jp + 1], ah[0], b4l + 2);
                mma_bf16(acc[1][2 * jp + 1], ah[1], b4l + 2);
                mma_bf16(acc[0][2 * jp],     al[0], b4h);
                mma_bf16(acc[1][2 * jp],     al[1], b4h);
                mma_bf16(acc[0][2 * jp + 1], al[0], b4h + 2);
                mma_bf16(acc[1][2 * jp + 1], al[1], b4h + 2);
            }
        }
        __syncthreads();
    }

    // epilogue
    const int qr = lid >> 2, qc = (lid & 3) << 1;
#pragma unroll
    for (int i = 0; i < 2; i++) {
#pragma unroll
        for (int j = 0; j < 8; j++) {
            int r0 = m0 + wm * 32 + i * 16 + qr;
            int c  = n0 + wn * 64 + j * 8 + qc;
#pragma unroll
            for (int hh = 0; hh < 2; hh++) {
                int m = r0 + hh * 8;
                float v0 = acc[i][j][2 * hh], v1 = acc[i][j][2 * hh + 1];
                if (MODE == 0) {
                    int bb = m >> 11, n = m & (SEQ - 1);
                    int which = c >> 10, cc = c & 1023;
                    int hd = cc >> 6, d = cc & 63;
                    size_t idx = ((size_t)(bb * NH + hd) * SEQ + n) * HD + d;
                    if (which == 0) { v0 *= QSCALE; v1 *= QSCALE; }
                    float h0 = bhi(v0), h1 = bhi(v1);
                    uint32_t uh = pack2(h0, h1);
                    uint32_t ul = pack2(v0 - h0, v1 - h1);
                    __nv_bfloat16* ph = (which == 0) ? g_Qh : (which == 1) ? g_Kh : g_Vh;
                    __nv_bfloat16* pl = (which == 0) ? g_Ql : (which == 1) ? g_Kl : g_Vl;
                    *reinterpret_cast<uint32_t*>(ph + idx) = uh;
                    *reinterpret_cast<uint32_t*>(pl + idx) = ul;
                } else {
                    float2 bv = *reinterpret_cast<const float2*>(bias + c);
                    float2 v = { v0 + bv.x, v1 + bv.y };
                    *reinterpret_cast<float2*>(Cout + (size_t)m * N + c) = v;
                }
            }
        }
    }
}

// ===========================================================================
// bf16x3 flash attention. Q kept in SMEM (re-ldsm per K-tile) to free 32
// regs -> __launch_bounds__(256,2) -> 2 CTAs/SM. Interleaved mma order.
// Smem: Q region (36864) + 2 KV stages (73728) = 110592 B/CTA.
// ===========================================================================
#define AST       72                       // smem row stride (bf16): 144B
#define ABUF      (64 * AST * 2)           // 9216 B per operand buffer
#define ASTAGE    (4 * ABUF)               // 36864 B per stage
#define QL_OFF    (128 * AST * 2)          // 18432: Ql after Qh
#define KV_OFF    (2 * QL_OFF)             // 36864: KV stages after Q
#define SMEM_ATTN (KV_OFF + 2 * ASTAGE)    // 110592 B

__device__ __forceinline__ void attn_cp_kv(
    uint32_t stage, const __nv_bfloat16* Kh, const __nv_bfloat16* Kl,
    const __nv_bfloat16* Vh, const __nv_bfloat16* Vl, int kt, int tid)
{
#pragma unroll
    for (int it = 0; it < 8; it++) {
        int slot = tid + (it << 8);          // 0..2047
        int buf  = slot >> 9;                // 0:Kh 1:Kl 2:Vh 3:Vl
        int s2   = slot & 511;
        int r    = s2 >> 3;                  // 0..63
        int c16  = s2 & 7;                   // 0..7
        const __nv_bfloat16* base = (buf == 0) ? Kh : (buf == 1) ? Kl
                                  : (buf == 2) ? Vh : Vl;
        cp16(stage + buf * ABUF + r * (AST * 2) + c16 * 16,
             base + (size_t)(kt * 64 + r) * HD + c16 * 8);
    }
}

__global__ __launch_bounds__(256, 2) void attn_mma()
{
    extern __shared__ __align__(16) char sma[];
    const uint32_t sb = smem_u32(sma);

    const int tid = threadIdx.x;
    const int lid = tid & 31;
    const int w   = tid >> 5;
    const int bh  = blockIdx.y;
    const int q0  = blockIdx.x << 7;

    const size_t hoff = (size_t)bh * SEQ * HD;
    const __nv_bfloat16* Qhp = g_Qh + hoff;
    const __nv_bfloat16* Qlp = g_Ql + hoff;
    const __nv_bfloat16* Khp = g_Kh + hoff;
    const __nv_bfloat16* Klp = g_Kl + hoff;
    const __nv_bfloat16* Vhp = g_Vh + hoff;
    const __nv_bfloat16* Vlp = g_Vl + hoff;

    // ---- stage Q (128 x 64 bf16, hi+lo) into persistent smem region ----
#pragma unroll
    for (int it = 0; it < 8; it++) {
        int slot = tid + (it << 8);          // 0..2047
        int half = slot >> 10;               // 0:h 1:l
        int s2   = slot & 1023;
        int r    = s2 >> 3;                  // 0..127
        int c16  = s2 & 7;
        const __nv_bfloat16* base = half ? Qlp : Qhp;
        cp16(sb + half * QL_OFF + r * (AST * 2) + c16 * 16,
             base + (size_t)(q0 + r) * HD + c16 * 8);
    }
    CP_COMMIT();

    float o[8][4];
#pragma unroll
    for (int j = 0; j < 8; j++)
#pragma unroll
        for (int v = 0; v < 4; v++) o[j][v] = 0.f;
    float mrow[2] = { -1e30f, -1e30f };
    float lrow[2] = { 0.f, 0.f };

    attn_cp_kv(sb + KV_OFF, Khp, Klp, Vhp, Vlp, 0, tid);
    CP_COMMIT();

#pragma unroll 1
    for (int kt = 0; kt < SEQ / 64; kt++) {
        if (kt + 1 < SEQ / 64) {
            attn_cp_kv(sb + KV_OFF + ((kt + 1) & 1) * ASTAGE,
                       Khp, Klp, Vhp, Vlp, kt + 1, tid);
            CP_COMMIT();
            CP_WAIT1();
        } else {
            CP_WAIT0();
        }
        __syncthreads();
        const uint32_t st = sb + KV_OFF + (kt & 1) * ASTAGE;

        // ---- S = Q @ K^T (Q frags re-lifted from smem per k4) ----
        float s[8][4];
#pragma unroll
        for (int j = 0; j < 8; j++)
#pragma unroll
            for (int v = 0; v < 4; v++) s[j][v] = 0.f;
#pragma unroll
        for (int k4 = 0; k4 < 4; k4++) {
            uint32_t q_h[4], q_l[4];
            uint32_t qoff = (uint32_t)((w * 16 + (lid & 15)) * AST
                                       + k4 * 16 + (lid >> 4) * 8) * 2;
            ldsm4(q_h, sb + qoff);
            ldsm4(q_l, sb + QL_OFF + qoff);
#pragma unroll
            for (int jp = 0; jp < 4; jp++) {
                int r = (2 * jp + ((lid >> 4) & 1)) * 8 + (lid & 7);
                int c = k4 * 16 + ((lid >> 3) & 1) * 8;
                uint32_t off = (uint32_t)(r * AST + c) * 2;
                uint32_t kh4[4], kl4[4];
                ldsm4(kh4, st + off);
                ldsm4(kl4, st + ABUF + off);
                mma_bf16(s[2 * jp],     q_h, kh4);
                mma_bf16(s[2 * jp + 1], q_h, kh4 + 2);
                mma_bf16(s[2 * jp],     q_h, kl4);
                mma_bf16(s[2 * jp + 1], q_h, kl4 + 2);
                mma_bf16(s[2 * jp],     q_l, kh4);
                mma_bf16(s[2 * jp + 1], q_l, kh4 + 2);
            }
        }

        // ---- online softmax (row halves qr and qr+8) ----
#pragma unroll
        for (int hh = 0; hh < 2; hh++) {
            float rm = -1e30f;
#pragma unroll
            for (int j = 0; j < 8; j++)
                rm = fmaxf(rm, fmaxf(s[j][2 * hh], s[j][2 * hh + 1]));
            rm = fmaxf(rm, __shfl_xor_sync(0xffffffffu, rm, 1));
            rm = fmaxf(rm, __shfl_xor_sync(0xffffffffu, rm, 2));
            float mnew = fmaxf(mrow[hh], rm);
            float corr = __expf(mrow[hh] - mnew);
            mrow[hh] = mnew;
            float ls = lrow[hh] * corr;
#pragma unroll
            for (int j = 0; j < 8; j++) {
                float p0 = __expf(s[j][2 * hh]     - mnew);
                float p1 = __expf(s[j][2 * hh + 1] - mnew);
                s[j][2 * hh] = p0; s[j][2 * hh + 1] = p1;
                ls += p0 + p1;
                o[j][2 * hh]     *= corr;
                o[j][2 * hh + 1] *= corr;
            }
            lrow[hh] = ls;
        }

        // ---- repack P into A-frags (hi/lo) ----
        uint32_t ph[4][4], pl[4][4];
#pragma unroll
        for (int t = 0; t < 4; t++) {
#pragma unroll
            for (int half = 0; half < 2; half++) {
                const float* sv = s[2 * t + half];
#pragma unroll
                for (int hh = 0; hh < 2; hh++) {
                    float p0 = sv[2 * hh], p1 = sv[2 * hh + 1];
                    float h0 = bhi(p0), h1 = bhi(p1);
                    ph[t][2 * half + hh] = pack2(h0, h1);
                    pl[t][2 * half + hh] = pack2(p0 - h0, p1 - h1);
                }
            }
        }

        // ---- O += P @ V (interleaved accumulators) ----
#pragma unroll
        for (int jp = 0; jp < 4; jp++) {
#pragma unroll
            for (int t = 0; t < 4; t++) {
                int r = t * 16 + (lid & 15);
                int c = (2 * jp + ((lid >> 4) & 1)) * 8;
                uint32_t off = (uint32_t)(r * AST + c) * 2;
                uint32_t vh4[4], vl4[4];
                ldsm4t(vh4, st + 2 * ABUF + off);
                ldsm4t(vl4, st + 3 * ABUF + off);
                mma_bf16(o[2 * jp],     ph[t], vh4);
                mma_bf16(o[2 * jp + 1], ph[t], vh4 + 2);
                mma_bf16(o[2 * jp],     ph[t], vl4);
                mma_bf16(o[2 * jp + 1], ph[t], vl4 + 2);
                mma_bf16(o[2 * jp],     pl[t], vh4);
                mma_bf16(o[2 * jp + 1], pl[t], vh4 + 2);
            }
        }
        __syncthreads();
    }

    // ---- epilogue: normalize, split hi/lo, write g_AOh/g_AOl [B,N,C] ----
#pragma unroll
    for (int hh = 0; hh < 2; hh++) {
        lrow[hh] += __shfl_xor_sync(0xffffffffu, lrow[hh], 1);
        lrow[hh] += __shfl_xor_sync(0xffffffffu, lrow[hh], 2);
    }
    const int bb = bh >> 4, hd = bh & 15;
    const int qr = lid >> 2, qc = (lid & 3) << 1;
#pragma unroll
    for (int hh = 0; hh < 2; hh++) {
        float inv = 1.f / lrow[hh];
        int n = q0 + w * 16 + qr + hh * 8;
        size_t base = ((size_t)(bb * SEQ + n)) * DIMC + hd * HD;
#pragma unroll
        for (int j = 0; j < 8; j++) {
            float v0 = o[j][2 * hh] * inv, v1 = o[j][2 * hh + 1] * inv;
            float h0 = bhi(v0), h1 = bhi(v1);
            *reinterpret_cast<uint32_t*>(g_AOh + base + j * 8 + qc) = pack2(h0, h1);
            *reinterpret_cast<uint32_t*>(g_AOl + base + j * 8 + qc) = pack2(v0 - h0, v1 - h1);
        }
    }
}

// ---------------------------------------------------------------------------
extern "C" void kernel_launch(void* const* d_in, const int* in_sizes, int n_in,
                              void* d_out, int out_size)
{
    const float* x      = (const float*)d_in[0];
    const float* w_qkv  = (const float*)d_in[1];
    const float* w_proj = (const float*)d_in[2];
    const float* b_proj = (const float*)d_in[3];
    float* out = (float*)d_out;

    __nv_bfloat16 *pXh, *pXl, *pWqh, *pWql, *pWph, *pWpl, *pAOh, *pAOl;
    cudaGetSymbolAddress((void**)&pXh,  g_Xh);
    cudaGetSymbolAddress((void**)&pXl,  g_Xl);
    cudaGetSymbolAddress((void**)&pWqh, g_Wqh);
    cudaGetSymbolAddress((void**)&pWql, g_Wql);
    cudaGetSymbolAddress((void**)&pWph, g_Wph);
    cudaGetSymbolAddress((void**)&pWpl, g_Wpl);
    cudaGetSymbolAddress((void**)&pAOh, g_AOh);
    cudaGetSymbolAddress((void**)&pAOl, g_AOl);

    cudaFuncSetAttribute(gemm_mma<0>,
                         cudaFuncAttributeMaxDynamicSharedMemorySize, SMEM_GEMM);
    cudaFuncSetAttribute(gemm_mma<1>,
                         cudaFuncAttributeMaxDynamicSharedMemorySize, SMEM_GEMM);
    cudaFuncSetAttribute(attn_mma,
                         cudaFuncAttributeMaxDynamicSharedMemorySize, SMEM_ATTN);

    // pre-split fp32 -> bf16 hi/lo
    int n4x = TOK * DIMC / 4, n4q = NQKV * DIMC / 4, n4p = DIMC * DIMC / 4;
    split_kernel<<<(n4x + 255) / 256, 256>>>(x, pXh, pXl, n4x);
    split_kernel<<<(n4q + 255) / 256, 256>>>(w_qkv, pWqh, pWql, n4q);
    split_kernel<<<(n4p + 255) / 256, 256>>>(w_proj, pWph, pWpl, n4p);

    dim3 g1(NQKV / 128, TOK / 128);      // (24, 64)
    gemm_mma<0><<<g1, 256, SMEM_GEMM>>>(pXh, pXl, pWqh, pWql,
                                        nullptr, nullptr, TOK, NQKV, DIMC);

    dim3 ga(SEQ / 128, BH);              // (16, 64)
    attn_mma<<<ga, 256, SMEM_ATTN>>>();

    dim3 g2(DIMC / 128, TOK / 128);      // (8, 64)
    gemm_mma<1><<<g2, 256, SMEM_GEMM>>>(pAOh, pAOl, pWph, pWpl,
                                        b_proj, out, TOK, DIMC, DIMC);
}

// round 15
// speedup vs baseline: 3.3858x; 1.0323x over previous
#include <cuda_runtime.h>
#include <cuda_bf16.h>
#include <cstdint>
#include <math.h>

// Problem constants
#define SEQ    2048
#define DIMC   1024
#define NH     16
#define HD     64
#define BATCH  4
#define BH     64          // BATCH*NH
#define TOK    8192        // BATCH*SEQ
#define NQKV   3072
#define QSCALE 0.125f      // 64^-0.5

// Persistent bf16 hi/lo scratch (allocation-free: __device__ globals)
__device__ __nv_bfloat16 g_Xh[(size_t)TOK * DIMC],  g_Xl[(size_t)TOK * DIMC];
__device__ __nv_bfloat16 g_Wqh[(size_t)NQKV * DIMC], g_Wql[(size_t)NQKV * DIMC];
__device__ __nv_bfloat16 g_Wph[(size_t)DIMC * DIMC], g_Wpl[(size_t)DIMC * DIMC];
__device__ __nv_bfloat16 g_Qh[(size_t)BH * SEQ * HD], g_Ql[(size_t)BH * SEQ * HD];
__device__ __nv_bfloat16 g_Kh[(size_t)BH * SEQ * HD], g_Kl[(size_t)BH * SEQ * HD];
__device__ __nv_bfloat16 g_Vh[(size_t)BH * SEQ * HD], g_Vl[(size_t)BH * SEQ * HD];
__device__ __nv_bfloat16 g_AOh[(size_t)TOK * DIMC],  g_AOl[(size_t)TOK * DIMC];

// ===========================================================================
// helpers (legal on base sm_103 target: mma.sync / ldmatrix / cp.async)
// ===========================================================================
__device__ __forceinline__ uint32_t smem_u32(const void* p) {
    uint32_t a;
    asm("{ .reg .u64 t; cvta.to.shared.u64 t, %1; cvt.u32.u64 %0, t; }"
        : "=r"(a) : "l"(p));
    return a;
}
__device__ __forceinline__ void mma_bf16(float* c, const uint32_t* a, const uint32_t* b) {
    asm volatile(
        "mma.sync.aligned.m16n8k16.row.col.f32.bf16.bf16.f32 "
        "{%0,%1,%2,%3}, {%4,%5,%6,%7}, {%8,%9}, {%0,%1,%2,%3};"
        : "+f"(c[0]), "+f"(c[1]), "+f"(c[2]), "+f"(c[3])
        : "r"(a[0]), "r"(a[1]), "r"(a[2]), "r"(a[3]), "r"(b[0]), "r"(b[1]));
}
__device__ __forceinline__ void ldsm4(uint32_t* r, uint32_t addr) {
    asm volatile("ldmatrix.sync.aligned.m8n8.x4.shared.b16 {%0,%1,%2,%3}, [%4];"
                 : "=r"(r[0]), "=r"(r[1]), "=r"(r[2]), "=r"(r[3]) : "r"(addr));
}
__device__ __forceinline__ void ldsm4t(uint32_t* r, uint32_t addr) {
    asm volatile("ldmatrix.sync.aligned.m8n8.x4.trans.shared.b16 {%0,%1,%2,%3}, [%4];"
                 : "=r"(r[0]), "=r"(r[1]), "=r"(r[2]), "=r"(r[3]) : "r"(addr));
}
__device__ __forceinline__ void cp16(uint32_t dst, const void* src) {
    asm volatile("cp.async.cg.shared.global [%0], [%1], 16;" :: "r"(dst), "l"(src));
}
#define CP_COMMIT()  asm volatile("cp.async.commit_group;" ::: "memory")
#define CP_WAIT0()   asm volatile("cp.async.wait_group 0;" ::: "memory")
#define CP_WAIT1()   asm volatile("cp.async.wait_group 1;" ::: "memory")

// pack two fp32 -> bf16x2 reg (lo lane = first arg)
__device__ __forceinline__ uint32_t pack2(float lo, float hi) {
    uint32_t r;
    asm("cvt.rn.bf16x2.f32 %0, %1, %2;" : "=r"(r) : "f"(hi), "f"(lo));
    return r;
}
__device__ __forceinline__ float bhi(float v) {
    return __bfloat162float(__float2bfloat16(v));
}

// ===========================================================================
// split kernel: fp32 -> bf16 hi + bf16 lo (residual)
// ===========================================================================
__global__ __launch_bounds__(256) void split_kernel(
    const float* __restrict__ in, __nv_bfloat16* __restrict__ oh,
    __nv_bfloat16* __restrict__ ol, int n4)
{
    int i = blockIdx.x * blockDim.x + threadIdx.x;
    if (i >= n4) return;
    float4 v = reinterpret_cast<const float4*>(in)[i];
    float hx = bhi(v.x), hy = bhi(v.y), hz = bhi(v.z), hw = bhi(v.w);
    uint2 uh = { pack2(hx, hy), pack2(hz, hw) };
    uint2 ul = { pack2(v.x - hx, v.y - hy), pack2(v.z - hz, v.w - hw) };
    reinterpret_cast<uint2*>(oh)[i] = uh;
    reinterpret_cast<uint2*>(ol)[i] = ul;
}

// ===========================================================================
// bf16x3 GEMM, 128x128 CTA, 2 CTAs/SM, cp.async double buffer (unchanged).
// ===========================================================================
#define GST       40                       // smem row stride (bf16): 80B
#define GBUF      (128 * GST * 2)          // 10240 B per operand buffer
#define GSTAGE    (4 * GBUF)               // 40960 B per stage
#define SMEM_GEMM (2 * GSTAGE)             // 81920 B

__device__ __forceinline__ void gemm_cp(
    uint32_t stage, const __nv_bfloat16* Ah, const __nv_bfloat16* Al,
    const __nv_bfloat16* Bh, const __nv_bfloat16* Bl,
    int m0, int n0, int k0, int K, int tid)
{
#pragma unroll
    for (int it = 0; it < 8; it++) {
        int slot = tid + (it << 8);          // 0..2047
        int buf  = slot >> 9;                // 0:Ah 1:Al 2:Bh 3:Bl
        int s2   = slot & 511;
        int r    = s2 >> 2;                  // 0..127
        int c16  = s2 & 3;                   // 0..3 (16B units)
        const __nv_bfloat16* base = (buf == 0) ? Ah : (buf == 1) ? Al
                                  : (buf == 2) ? Bh : Bl;
        int row = ((buf < 2) ? m0 : n0) + r;
        cp16(stage + buf * GBUF + r * (GST * 2) + c16 * 16,
             base + (size_t)row * K + k0 + c16 * 8);
    }
}

template <int MODE>
__global__ __launch_bounds__(256, 2) void gemm_mma(
    const __nv_bfloat16* __restrict__ Ah, const __nv_bfloat16* __restrict__ Al,
    const __nv_bfloat16* __restrict__ Bh, const __nv_bfloat16* __restrict__ Bl,
    const float* __restrict__ bias, float* __restrict__ Cout,
    int M, int N, int K)
{
    extern __shared__ __align__(16) char smg[];
    const uint32_t sb = smem_u32(smg);

    const int tid = threadIdx.x;
    const int lid = tid & 31;
    const int wid = tid >> 5;
    const int wm = wid & 3;
    const int wn = wid >> 2;
    const int m0 = blockIdx.y << 7;
    const int n0 = blockIdx.x << 7;

    float acc[2][8][4];
#pragma unroll
    for (int i = 0; i < 2; i++)
#pragma unroll
        for (int j = 0; j < 8; j++)
#pragma unroll
            for (int v = 0; v < 4; v++) acc[i][j][v] = 0.f;

    const uint32_t aoffs[2] = {
        (uint32_t)((wm * 32 + (lid & 15)) * GST + (lid >> 4) * 8) * 2,
        (uint32_t)((wm * 32 + 16 + (lid & 15)) * GST + (lid >> 4) * 8) * 2 };
    uint32_t boffs[4];
#pragma unroll
    for (int jp = 0; jp < 4; jp++)
        boffs[jp] = (uint32_t)((wn * 64 + (2 * jp + ((lid >> 4) & 1)) * 8 + (lid & 7)) * GST
                               + ((lid >> 3) & 1) * 8) * 2;

    const int nchunks = K >> 5;
    gemm_cp(sb, Ah, Al, Bh, Bl, m0, n0, 0, K, tid);
    CP_COMMIT();

#pragma unroll 1
    for (int t = 0; t < nchunks; ++t) {
        if (t + 1 < nchunks) {
            gemm_cp(sb + ((t + 1) & 1) * GSTAGE, Ah, Al, Bh, Bl,
                    m0, n0, (t + 1) << 5, K, tid);
            CP_COMMIT();
            CP_WAIT1();
        } else {
            CP_WAIT0();
        }
        __syncthreads();

        const uint32_t st = sb + (t & 1) * GSTAGE;
#pragma unroll
        for (int ks = 0; ks < 2; ks++) {
            const uint32_t kso = (uint32_t)(ks * 16) * 2;
            uint32_t ah[2][4], al[2][4];
#pragma unroll
            for (int i = 0; i < 2; i++) {
                ldsm4(ah[i], st + aoffs[i] + kso);
                ldsm4(al[i], st + GBUF + aoffs[i] + kso);
            }
#pragma unroll
            for (int jp = 0; jp < 4; jp++) {
                uint32_t b4h[4], b4l[4];
                ldsm4(b4h, st + 2 * GBUF + boffs[jp] + kso);
                ldsm4(b4l, st + 3 * GBUF + boffs[jp] + kso);
                mma_bf16(acc[0][2 * jp],     ah[0], b4h);
                mma_bf16(acc[1][2 * jp],     ah[1], b4h);
                mma_bf16(acc[0][2 * jp + 1], ah[0], b4h + 2);
                mma_bf16(acc[1][2 * jp + 1], ah[1], b4h + 2);
                mma_bf16(acc[0][2 * jp],     ah[0], b4l);
                mma_bf16(acc[1][2 * jp],     ah[1], b4l);
                mma_bf16(acc[0][2 * jp + 1], ah[0], b4l + 2);
                mma_bf16(acc[1][2 * jp + 1], ah[1], b4l + 2);
                mma_bf16(acc[0][2 * jp],     al[0], b4h);
                mma_bf16(acc[1][2 * jp],     al[1], b4h);
                mma_bf16(acc[0][2 * jp + 1], al[0], b4h + 2);
                mma_bf16(acc[1][2 * jp + 1], al[1], b4h + 2);
            }
        }
        __syncthreads();
    }

    // epilogue
    const int qr = lid >> 2, qc = (lid & 3) << 1;
#pragma unroll
    for (int i = 0; i < 2; i++) {
#pragma unroll
        for (int j = 0; j < 8; j++) {
            int r0 = m0 + wm * 32 + i * 16 + qr;
            int c  = n0 + wn * 64 + j * 8 + qc;
#pragma unroll
            for (int hh = 0; hh < 2; hh++) {
                int m = r0 + hh * 8;
                float v0 = acc[i][j][2 * hh], v1 = acc[i][j][2 * hh + 1];
                if (MODE == 0) {
                    int bb = m >> 11, n = m & (SEQ - 1);
                    int which = c >> 10, cc = c & 1023;
                    int hd = cc >> 6, d = cc & 63;
                    size_t idx = ((size_t)(bb * NH + hd) * SEQ + n) * HD + d;
                    if (which == 0) { v0 *= QSCALE; v1 *= QSCALE; }
                    float h0 = bhi(v0), h1 = bhi(v1);
                    uint32_t uh = pack2(h0, h1);
                    uint32_t ul = pack2(v0 - h0, v1 - h1);
                    __nv_bfloat16* ph = (which == 0) ? g_Qh : (which == 1) ? g_Kh : g_Vh;
                    __nv_bfloat16* pl = (which == 0) ? g_Ql : (which == 1) ? g_Kl : g_Vl;
                    *reinterpret_cast<uint32_t*>(ph + idx) = uh;
                    *reinterpret_cast<uint32_t*>(pl + idx) = ul;
                } else {
                    float2 bv = *reinterpret_cast<const float2*>(bias + c);
                    float2 v = { v0 + bv.x, v1 + bv.y };
                    *reinterpret_cast<float2*>(Cout + (size_t)m * N + c) = v;
                }
            }
        }
    }
}

// ===========================================================================
// bf16x3 flash attention. NOW: 128 threads, 4 warps x 32 q-rows each
// (was 8 x 16): halves K/V ldmatrix duplication and softmax/sync overhead
// per MMA. Q in smem; 2 CTAs/SM (smem 110592 x 2 = 221184 <= 228K).
// ===========================================================================
#define AST       72                       // smem row stride (bf16): 144B
#define ABUF      (64 * AST * 2)           // 9216 B per operand buffer
#define ASTAGE    (4 * ABUF)               // 36864 B per stage
#define QL_OFF    (128 * AST * 2)          // 18432: Ql after Qh
#define KV_OFF    (2 * QL_OFF)             // 36864: KV stages after Q
#define SMEM_ATTN (KV_OFF + 2 * ASTAGE)    // 110592 B
#define ATHREADS  128

__device__ __forceinline__ void attn_cp_kv(
    uint32_t stage, const __nv_bfloat16* Kh, const __nv_bfloat16* Kl,
    const __nv_bfloat16* Vh, const __nv_bfloat16* Vl, int kt, int tid)
{
#pragma unroll
    for (int it = 0; it < 16; it++) {
        int slot = tid + (it << 7);          // 0..2047
        int buf  = slot >> 9;                // 0:Kh 1:Kl 2:Vh 3:Vl
        int s2   = slot & 511;
        int r    = s2 >> 3;                  // 0..63
        int c16  = s2 & 7;                   // 0..7
        const __nv_bfloat16* base = (buf == 0) ? Kh : (buf == 1) ? Kl
                                  : (buf == 2) ? Vh : Vl;
        cp16(stage + buf * ABUF + r * (AST * 2) + c16 * 16,
             base + (size_t)(kt * 64 + r) * HD + c16 * 8);
    }
}

__global__ __launch_bounds__(ATHREADS, 2) void attn_mma()
{
    extern __shared__ __align__(16) char sma[];
    const uint32_t sb = smem_u32(sma);

    const int tid = threadIdx.x;
    const int lid = tid & 31;
    const int w   = tid >> 5;          // 0..3, each owns 32 q-rows
    const int bh  = blockIdx.y;
    const int q0  = blockIdx.x << 7;

    const size_t hoff = (size_t)bh * SEQ * HD;
    const __nv_bfloat16* Qhp = g_Qh + hoff;
    const __nv_bfloat16* Qlp = g_Ql + hoff;
    const __nv_bfloat16* Khp = g_Kh + hoff;
    const __nv_bfloat16* Klp = g_Kl + hoff;
    const __nv_bfloat16* Vhp = g_Vh + hoff;
    const __nv_bfloat16* Vlp = g_Vl + hoff;

    // ---- stage Q (128 x 64 bf16, hi+lo) into persistent smem region ----
#pragma unroll
    for (int it = 0; it < 16; it++) {
        int slot = tid + (it << 7);          // 0..2047
        int half = slot >> 10;               // 0:h 1:l
        int s2   = slot & 1023;
        int r    = s2 >> 3;                  // 0..127
        int c16  = s2 & 7;
        const __nv_bfloat16* base = half ? Qlp : Qhp;
        cp16(sb + half * QL_OFF + r * (AST * 2) + c16 * 16,
             base + (size_t)(q0 + r) * HD + c16 * 8);
    }
    CP_COMMIT();

    float o[2][8][4];
#pragma unroll
    for (int i = 0; i < 2; i++)
#pragma unroll
        for (int j = 0; j < 8; j++)
#pragma unroll
            for (int v = 0; v < 4; v++) o[i][j][v] = 0.f;
    float mrow[2][2] = { { -1e30f, -1e30f }, { -1e30f, -1e30f } };
    float lrow[2][2] = { { 0.f, 0.f }, { 0.f, 0.f } };

    attn_cp_kv(sb + KV_OFF, Khp, Klp, Vhp, Vlp, 0, tid);
    CP_COMMIT();

#pragma unroll 1
    for (int kt = 0; kt < SEQ / 64; kt++) {
        if (kt + 1 < SEQ / 64) {
            attn_cp_kv(sb + KV_OFF + ((kt + 1) & 1) * ASTAGE,
                       Khp, Klp, Vhp, Vlp, kt + 1, tid);
            CP_COMMIT();
            CP_WAIT1();
        } else {
            CP_WAIT0();
        }
        __syncthreads();
        const uint32_t st = sb + KV_OFF + (kt & 1) * ASTAGE;

        // ---- S = Q @ K^T : 2 m-tiles x 8 n8-tiles ----
        float s[2][8][4];
#pragma unroll
        for (int i = 0; i < 2; i++)
#pragma unroll
            for (int j = 0; j < 8; j++)
#pragma unroll
                for (int v = 0; v < 4; v++) s[i][j][v] = 0.f;
#pragma unroll
        for (int k4 = 0; k4 < 4; k4++) {
            uint32_t q_h[2][4], q_l[2][4];
#pragma unroll
            for (int i = 0; i < 2; i++) {
                uint32_t qoff = (uint32_t)((w * 32 + i * 16 + (lid & 15)) * AST
                                           + k4 * 16 + (lid >> 4) * 8) * 2;
                ldsm4(q_h[i], sb + qoff);
                ldsm4(q_l[i], sb + QL_OFF + qoff);
            }
#pragma unroll
            for (int jp = 0; jp < 4; jp++) {
                int r = (2 * jp + ((lid >> 4) & 1)) * 8 + (lid & 7);
                int c = k4 * 16 + ((lid >> 3) & 1) * 8;
                uint32_t off = (uint32_t)(r * AST + c) * 2;
                uint32_t kh4[4], kl4[4];
                ldsm4(kh4, st + off);
                ldsm4(kl4, st + ABUF + off);
                mma_bf16(s[0][2 * jp],     q_h[0], kh4);
                mma_bf16(s[1][2 * jp],     q_h[1], kh4);
                mma_bf16(s[0][2 * jp + 1], q_h[0], kh4 + 2);
                mma_bf16(s[1][2 * jp + 1], q_h[1], kh4 + 2);
                mma_bf16(s[0][2 * jp],     q_h[0], kl4);
                mma_bf16(s[1][2 * jp],     q_h[1], kl4);
                mma_bf16(s[0][2 * jp + 1], q_h[0], kl4 + 2);
                mma_bf16(s[1][2 * jp + 1], q_h[1], kl4 + 2);
                mma_bf16(s[0][2 * jp],     q_l[0], kh4);
                mma_bf16(s[1][2 * jp],     q_l[1], kh4);
                mma_bf16(s[0][2 * jp + 1], q_l[0], kh4 + 2);
                mma_bf16(s[1][2 * jp + 1], q_l[1], kh4 + 2);
            }
        }

        // ---- online softmax (per m-tile, per row-half) ----
#pragma unroll
        for (int i = 0; i < 2; i++) {
#pragma unroll
            for (int hh = 0; hh < 2; hh++) {
                float rm = -1e30f;
#pragma unroll
                for (int j = 0; j < 8; j++)
                    rm = fmaxf(rm, fmaxf(s[i][j][2 * hh], s[i][j][2 * hh + 1]));
                rm = fmaxf(rm, __shfl_xor_sync(0xffffffffu, rm, 1));
                rm = fmaxf(rm, __shfl_xor_sync(0xffffffffu, rm, 2));
                float mnew = fmaxf(mrow[i][hh], rm);
                float corr = __expf(mrow[i][hh] - mnew);
                mrow[i][hh] = mnew;
                float ls = lrow[i][hh] * corr;
#pragma unroll
                for (int j = 0; j < 8; j++) {
                    float p0 = __expf(s[i][j][2 * hh]     - mnew);
                    float p1 = __expf(s[i][j][2 * hh + 1] - mnew);
                    s[i][j][2 * hh] = p0; s[i][j][2 * hh + 1] = p1;
                    ls += p0 + p1;
                    o[i][j][2 * hh]     *= corr;
                    o[i][j][2 * hh + 1] *= corr;
                }
                lrow[i][hh] = ls;
            }
        }

        // ---- repack P into A-frags (hi/lo) ----
        uint32_t ph[2][4][4], pl[2][4][4];
#pragma unroll
        for (int i = 0; i < 2; i++) {
#pragma unroll
            for (int t = 0; t < 4; t++) {
#pragma unroll
                for (int half = 0; half < 2; half++) {
                    const float* sv = s[i][2 * t + half];
#pragma unroll
                    for (int hh = 0; hh < 2; hh++) {
                        float p0 = sv[2 * hh], p1 = sv[2 * hh + 1];
                        float h0 = bhi(p0), h1 = bhi(p1);
                        ph[i][t][2 * half + hh] = pack2(h0, h1);
                        pl[i][t][2 * half + hh] = pack2(p0 - h0, p1 - h1);
                    }
                }
            }
        }

        // ---- O += P @ V (V frags shared across both m-tiles) ----
#pragma unroll
        for (int jp = 0; jp < 4; jp++) {
#pragma unroll
            for (int t = 0; t < 4; t++) {
                int r = t * 16 + (lid & 15);
                int c = (2 * jp + ((lid >> 4) & 1)) * 8;
                uint32_t off = (uint32_t)(r * AST + c) * 2;
                uint32_t vh4[4], vl4[4];
                ldsm4t(vh4, st + 2 * ABUF + off);
                ldsm4t(vl4, st + 3 * ABUF + off);
                mma_bf16(o[0][2 * jp],     ph[0][t], vh4);
                mma_bf16(o[1][2 * jp],     ph[1][t], vh4);
                mma_bf16(o[0][2 * jp + 1], ph[0][t], vh4 + 2);
                mma_bf16(o[1][2 * jp + 1], ph[1][t], vh4 + 2);
                mma_bf16(o[0][2 * jp],     ph[0][t], vl4);
                mma_bf16(o[1][2 * jp],     ph[1][t], vl4);
                mma_bf16(o[0][2 * jp + 1], ph[0][t], vl4 + 2);
                mma_bf16(o[1][2 * jp + 1], ph[1][t], vl4 + 2);
                mma_bf16(o[0][2 * jp],     pl[0][t], vh4);
                mma_bf16(o[1][2 * jp],     pl[1][t], vh4);
                mma_bf16(o[0][2 * jp + 1], pl[0][t], vh4 + 2);
                mma_bf16(o[1][2 * jp + 1], pl[1][t], vh4 + 2);
            }
        }
        __syncthreads();
    }

    // ---- epilogue: normalize, split hi/lo, write g_AOh/g_AOl [B,N,C] ----
    const int bb = bh >> 4, hd = bh & 15;
    const int qr = lid >> 2, qc = (lid & 3) << 1;
#pragma unroll
    for (int i = 0; i < 2; i++) {
#pragma unroll
        for (int hh = 0; hh < 2; hh++) {
            float lr = lrow[i][hh];
            lr += __shfl_xor_sync(0xffffffffu, lr, 1);
            lr += __shfl_xor_sync(0xffffffffu, lr, 2);
            float inv = 1.f / lr;
            int n = q0 + w * 32 + i * 16 + qr + hh * 8;
            size_t base = ((size_t)(bb * SEQ + n)) * DIMC + hd * HD;
#pragma unroll
            for (int j = 0; j < 8; j++) {
                float v0 = o[i][j][2 * hh] * inv, v1 = o[i][j][2 * hh + 1] * inv;
                float h0 = bhi(v0), h1 = bhi(v1);
                *reinterpret_cast<uint32_t*>(g_AOh + base + j * 8 + qc) = pack2(h0, h1);
                *reinterpret_cast<uint32_t*>(g_AOl + base + j * 8 + qc) = pack2(v0 - h0, v1 - h1);
            }
        }
    }
}

// ---------------------------------------------------------------------------
extern "C" void kernel_launch(void* const* d_in, const int* in_sizes, int n_in,
                              void* d_out, int out_size)
{
    const float* x      = (const float*)d_in[0];
    const float* w_qkv  = (const float*)d_in[1];
    const float* w_proj = (const float*)d_in[2];
    const float* b_proj = (const float*)d_in[3];
    float* out = (float*)d_out;

    __nv_bfloat16 *pXh, *pXl, *pWqh, *pWql, *pWph, *pWpl, *pAOh, *pAOl;
    cudaGetSymbolAddress((void**)&pXh,  g_Xh);
    cudaGetSymbolAddress((void**)&pXl,  g_Xl);
    cudaGetSymbolAddress((void**)&pWqh, g_Wqh);
    cudaGetSymbolAddress((void**)&pWql, g_Wql);
    cudaGetSymbolAddress((void**)&pWph, g_Wph);
    cudaGetSymbolAddress((void**)&pWpl, g_Wpl);
    cudaGetSymbolAddress((void**)&pAOh, g_AOh);
    cudaGetSymbolAddress((void**)&pAOl, g_AOl);

    cudaFuncSetAttribute(gemm_mma<0>,
                         cudaFuncAttributeMaxDynamicSharedMemorySize, SMEM_GEMM);
    cudaFuncSetAttribute(gemm_mma<1>,
                         cudaFuncAttributeMaxDynamicSharedMemorySize, SMEM_GEMM);
    cudaFuncSetAttribute(attn_mma,
                         cudaFuncAttributeMaxDynamicSharedMemorySize, SMEM_ATTN);

    // pre-split fp32 -> bf16 hi/lo
    int n4x = TOK * DIMC / 4, n4q = NQKV * DIMC / 4, n4p = DIMC * DIMC / 4;
    split_kernel<<<(n4x + 255) / 256, 256>>>(x, pXh, pXl, n4x);
    split_kernel<<<(n4q + 255) / 256, 256>>>(w_qkv, pWqh, pWql, n4q);
    split_kernel<<<(n4p + 255) / 256, 256>>>(w_proj, pWph, pWpl, n4p);

    dim3 g1(NQKV / 128, TOK / 128);      // (24, 64)
    gemm_mma<0><<<g1, 256, SMEM_GEMM>>>(pXh, pXl, pWqh, pWql,
                                        nullptr, nullptr, TOK, NQKV, DIMC);

    dim3 ga(SEQ / 128, BH);              // (16, 64)
    attn_mma<<<ga, ATHREADS, SMEM_ATTN>>>();

    dim3 g2(DIMC / 128, TOK / 128);      // (8, 64)
    gemm_mma<1><<<g2, 256, SMEM_GEMM>>>(pAOh, pAOl, pWph, pWpl,
                                        b_proj, out, TOK, DIMC, DIMC);
}

// round 16
// speedup vs baseline: 3.4062x; 1.0060x over previous
#include <cuda_runtime.h>
#include <cuda_bf16.h>
#include <cstdint>
#include <math.h>

// Problem constants
#define SEQ    2048
#define DIMC   1024
#define NH     16
#define HD     64
#define BATCH  4
#define BH     64          // BATCH*NH
#define TOK    8192        // BATCH*SEQ
#define NQKV   3072
#define QSCALE 0.125f      // 64^-0.5

// Persistent bf16 hi/lo scratch (allocation-free: __device__ globals)
__device__ __nv_bfloat16 g_Xh[(size_t)TOK * DIMC],  g_Xl[(size_t)TOK * DIMC];
__device__ __nv_bfloat16 g_Wqh[(size_t)NQKV * DIMC], g_Wql[(size_t)NQKV * DIMC];
__device__ __nv_bfloat16 g_Wph[(size_t)DIMC * DIMC], g_Wpl[(size_t)DIMC * DIMC];
__device__ __nv_bfloat16 g_Qh[(size_t)BH * SEQ * HD], g_Ql[(size_t)BH * SEQ * HD];
__device__ __nv_bfloat16 g_Kh[(size_t)BH * SEQ * HD], g_Kl[(size_t)BH * SEQ * HD];
__device__ __nv_bfloat16 g_Vh[(size_t)BH * SEQ * HD], g_Vl[(size_t)BH * SEQ * HD];
__device__ __nv_bfloat16 g_AOh[(size_t)TOK * DIMC],  g_AOl[(size_t)TOK * DIMC];

// ===========================================================================
// helpers (legal on base sm_103 target: mma.sync / ldmatrix / cp.async)
// ===========================================================================
__device__ __forceinline__ uint32_t smem_u32(const void* p) {
    uint32_t a;
    asm("{ .reg .u64 t; cvta.to.shared.u64 t, %1; cvt.u32.u64 %0, t; }"
        : "=r"(a) : "l"(p));
    return a;
}
__device__ __forceinline__ void mma_bf16(float* c, const uint32_t* a, const uint32_t* b) {
    asm volatile(
        "mma.sync.aligned.m16n8k16.row.col.f32.bf16.bf16.f32 "
        "{%0,%1,%2,%3}, {%4,%5,%6,%7}, {%8,%9}, {%0,%1,%2,%3};"
        : "+f"(c[0]), "+f"(c[1]), "+f"(c[2]), "+f"(c[3])
        : "r"(a[0]), "r"(a[1]), "r"(a[2]), "r"(a[3]), "r"(b[0]), "r"(b[1]));
}
__device__ __forceinline__ void ldsm4(uint32_t* r, uint32_t addr) {
    asm volatile("ldmatrix.sync.aligned.m8n8.x4.shared.b16 {%0,%1,%2,%3}, [%4];"
                 : "=r"(r[0]), "=r"(r[1]), "=r"(r[2]), "=r"(r[3]) : "r"(addr));
}
__device__ __forceinline__ void ldsm4t(uint32_t* r, uint32_t addr) {
    asm volatile("ldmatrix.sync.aligned.m8n8.x4.trans.shared.b16 {%0,%1,%2,%3}, [%4];"
                 : "=r"(r[0]), "=r"(r[1]), "=r"(r[2]), "=r"(r[3]) : "r"(addr));
}
__device__ __forceinline__ void cp16(uint32_t dst, const void* src) {
    asm volatile("cp.async.cg.shared.global [%0], [%1], 16;" :: "r"(dst), "l"(src));
}
#define CP_COMMIT()  asm volatile("cp.async.commit_group;" ::: "memory")
#define CP_WAIT0()   asm volatile("cp.async.wait_group 0;" ::: "memory")

// pack two fp32 -> bf16x2 reg (lo lane = first arg)
__device__ __forceinline__ uint32_t pack2(float lo, float hi) {
    uint32_t r;
    asm("cvt.rn.bf16x2.f32 %0, %1, %2;" : "=r"(r) : "f"(hi), "f"(lo));
    return r;
}
__device__ __forceinline__ float bhi(float v) {
    return __bfloat162float(__float2bfloat16(v));
}

// ===========================================================================
// split kernel: fp32 -> bf16 hi + bf16 lo (residual)
// ===========================================================================
__global__ __launch_bounds__(256) void split_kernel(
    const float* __restrict__ in, __nv_bfloat16* __restrict__ oh,
    __nv_bfloat16* __restrict__ ol, int n4)
{
    int i = blockIdx.x * blockDim.x + threadIdx.x;
    if (i >= n4) return;
    float4 v = reinterpret_cast<const float4*>(in)[i];
    float hx = bhi(v.x), hy = bhi(v.y), hz = bhi(v.z), hw = bhi(v.w);
    uint2 uh = { pack2(hx, hy), pack2(hz, hw) };
    uint2 ul = { pack2(v.x - hx, v.y - hy), pack2(v.z - hz, v.w - hw) };
    reinterpret_cast<uint2*>(oh)[i] = uh;
    reinterpret_cast<uint2*>(ol)[i] = ul;
}

// ===========================================================================
// bf16x3 GEMM, 128x128 CTA, 2 CTAs/SM, cp.async double buffer.
// ONE __syncthreads per K-chunk (wait -> sync -> cp-next -> mma) and
// ping-pong B-fragment prefetch (load jp+1 while mma-ing jp).
// ===========================================================================
#define GST       40                       // smem row stride (bf16): 80B
#define GBUF      (128 * GST * 2)          // 10240 B per operand buffer
#define GSTAGE    (4 * GBUF)               // 40960 B per stage
#define SMEM_GEMM (2 * GSTAGE)             // 81920 B

__device__ __forceinline__ void gemm_cp(
    uint32_t stage, const __nv_bfloat16* Ah, const __nv_bfloat16* Al,
    const __nv_bfloat16* Bh, const __nv_bfloat16* Bl,
    int m0, int n0, int k0, int K, int tid)
{
#pragma unroll
    for (int it = 0; it < 8; it++) {
        int slot = tid + (it << 8);          // 0..2047
        int buf  = slot >> 9;                // 0:Ah 1:Al 2:Bh 3:Bl
        int s2   = slot & 511;
        int r    = s2 >> 2;                  // 0..127
        int c16  = s2 & 3;                   // 0..3 (16B units)
        const __nv_bfloat16* base = (buf == 0) ? Ah : (buf == 1) ? Al
                                  : (buf == 2) ? Bh : Bl;
        int row = ((buf < 2) ? m0 : n0) + r;
        cp16(stage + buf * GBUF + r * (GST * 2) + c16 * 16,
             base + (size_t)row * K + k0 + c16 * 8);
    }
}

template <int MODE>
__global__ __launch_bounds__(256, 2) void gemm_mma(
    const __nv_bfloat16* __restrict__ Ah, const __nv_bfloat16* __restrict__ Al,
    const __nv_bfloat16* __restrict__ Bh, const __nv_bfloat16* __restrict__ Bl,
    const float* __restrict__ bias, float* __restrict__ Cout,
    int M, int N, int K)
{
    extern __shared__ __align__(16) char smg[];
    const uint32_t sb = smem_u32(smg);

    const int tid = threadIdx.x;
    const int lid = tid & 31;
    const int wid = tid >> 5;
    const int wm = wid & 3;
    const int wn = wid >> 2;
    const int m0 = blockIdx.y << 7;
    const int n0 = blockIdx.x << 7;

    float acc[2][8][4];
#pragma unroll
    for (int i = 0; i < 2; i++)
#pragma unroll
        for (int j = 0; j < 8; j++)
#pragma unroll
            for (int v = 0; v < 4; v++) acc[i][j][v] = 0.f;

    const uint32_t aoffs[2] = {
        (uint32_t)((wm * 32 + (lid & 15)) * GST + (lid >> 4) * 8) * 2,
        (uint32_t)((wm * 32 + 16 + (lid & 15)) * GST + (lid >> 4) * 8) * 2 };
    uint32_t boffs[4];
#pragma unroll
    for (int jp = 0; jp < 4; jp++)
        boffs[jp] = (uint32_t)((wn * 64 + (2 * jp + ((lid >> 4) & 1)) * 8 + (lid & 7)) * GST
                               + ((lid >> 3) & 1) * 8) * 2;

    const int nchunks = K >> 5;
    gemm_cp(sb, Ah, Al, Bh, Bl, m0, n0, 0, K, tid);
    CP_COMMIT();

#pragma unroll 1
    for (int t = 0; t < nchunks; ++t) {
        CP_WAIT0();
        __syncthreads();    // stage t%2 landed; all warps done reading t-1

        if (t + 1 < nchunks) {
            gemm_cp(sb + ((t + 1) & 1) * GSTAGE, Ah, Al, Bh, Bl,
                    m0, n0, (t + 1) << 5, K, tid);
            CP_COMMIT();
        }

        const uint32_t st = sb + (t & 1) * GSTAGE;
#pragma unroll
        for (int ks = 0; ks < 2; ks++) {
            const uint32_t kso = (uint32_t)(ks * 16) * 2;
            uint32_t ah[2][4], al[2][4];
            ldsm4(ah[0], st + aoffs[0] + kso);
            ldsm4(ah[1], st + aoffs[1] + kso);
            ldsm4(al[0], st + GBUF + aoffs[0] + kso);
            ldsm4(al[1], st + GBUF + aoffs[1] + kso);
            uint32_t b4h[2][4], b4l[2][4];
            ldsm4(b4h[0], st + 2 * GBUF + boffs[0] + kso);
            ldsm4(b4l[0], st + 3 * GBUF + boffs[0] + kso);
#pragma unroll
            for (int jp = 0; jp < 4; jp++) {
                const int cur = jp & 1, nxt = cur ^ 1;
                if (jp < 3) {     // prefetch next B-frags while mma-ing these
                    ldsm4(b4h[nxt], st + 2 * GBUF + boffs[jp + 1] + kso);
                    ldsm4(b4l[nxt], st + 3 * GBUF + boffs[jp + 1] + kso);
                }
                mma_bf16(acc[0][2 * jp],     ah[0], b4h[cur]);
                mma_bf16(acc[1][2 * jp],     ah[1], b4h[cur]);
                mma_bf16(acc[0][2 * jp + 1], ah[0], b4h[cur] + 2);
                mma_bf16(acc[1][2 * jp + 1], ah[1], b4h[cur] + 2);
                mma_bf16(acc[0][2 * jp],     ah[0], b4l[cur]);
                mma_bf16(acc[1][2 * jp],     ah[1], b4l[cur]);
                mma_bf16(acc[0][2 * jp + 1], ah[0], b4l[cur] + 2);
                mma_bf16(acc[1][2 * jp + 1], ah[1], b4l[cur] + 2);
                mma_bf16(acc[0][2 * jp],     al[0], b4h[cur]);
                mma_bf16(acc[1][2 * jp],     al[1], b4h[cur]);
                mma_bf16(acc[0][2 * jp + 1], al[0], b4h[cur] + 2);
                mma_bf16(acc[1][2 * jp + 1], al[1], b4h[cur] + 2);
            }
        }
    }

    // epilogue
    const int qr = lid >> 2, qc = (lid & 3) << 1;
#pragma unroll
    for (int i = 0; i < 2; i++) {
#pragma unroll
        for (int j = 0; j < 8; j++) {
            int r0 = m0 + wm * 32 + i * 16 + qr;
            int c  = n0 + wn * 64 + j * 8 + qc;
#pragma unroll
            for (int hh = 0; hh < 2; hh++) {
                int m = r0 + hh * 8;
                float v0 = acc[i][j][2 * hh], v1 = acc[i][j][2 * hh + 1];
                if (MODE == 0) {
                    int bb = m >> 11, n = m & (SEQ - 1);
                    int which = c >> 10, cc = c & 1023;
                    int hd = cc >> 6, d = cc & 63;
                    size_t idx = ((size_t)(bb * NH + hd) * SEQ + n) * HD + d;
                    if (which == 0) { v0 *= QSCALE; v1 *= QSCALE; }
                    float h0 = bhi(v0), h1 = bhi(v1);
                    uint32_t uh = pack2(h0, h1);
                    uint32_t ul = pack2(v0 - h0, v1 - h1);
                    __nv_bfloat16* ph = (which == 0) ? g_Qh : (which == 1) ? g_Kh : g_Vh;
                    __nv_bfloat16* pl = (which == 0) ? g_Ql : (which == 1) ? g_Kl : g_Vl;
                    *reinterpret_cast<uint32_t*>(ph + idx) = uh;
                    *reinterpret_cast<uint32_t*>(pl + idx) = ul;
                } else {
                    float2 bv = *reinterpret_cast<const float2*>(bias + c);
                    float2 v = { v0 + bv.x, v1 + bv.y };
                    *reinterpret_cast<float2*>(Cout + (size_t)m * N + c) = v;
                }
            }
        }
    }
}

// ===========================================================================
// bf16x3 flash attention: 128 threads, 4 warps x 32 q-rows, Q in smem,
// 2 CTAs/SM. ONE __syncthreads per KV-tile; ping-pong K/V frag prefetch.
// ===========================================================================
#define AST       72                       // smem row stride (bf16): 144B
#define ABUF      (64 * AST * 2)           // 9216 B per operand buffer
#define ASTAGE    (4 * ABUF)               // 36864 B per stage
#define QL_OFF    (128 * AST * 2)          // 18432: Ql after Qh
#define KV_OFF    (2 * QL_OFF)             // 36864: KV stages after Q
#define SMEM_ATTN (KV_OFF + 2 * ASTAGE)    // 110592 B
#define ATHREADS  128

__device__ __forceinline__ void attn_cp_kv(
    uint32_t stage, const __nv_bfloat16* Kh, const __nv_bfloat16* Kl,
    const __nv_bfloat16* Vh, const __nv_bfloat16* Vl, int kt, int tid)
{
#pragma unroll
    for (int it = 0; it < 16; it++) {
        int slot = tid + (it << 7);          // 0..2047
        int buf  = slot >> 9;                // 0:Kh 1:Kl 2:Vh 3:Vl
        int s2   = slot & 511;
        int r    = s2 >> 3;                  // 0..63
        int c16  = s2 & 7;                   // 0..7
        const __nv_bfloat16* base = (buf == 0) ? Kh : (buf == 1) ? Kl
                                  : (buf == 2) ? Vh : Vl;
        cp16(stage + buf * ABUF + r * (AST * 2) + c16 * 16,
             base + (size_t)(kt * 64 + r) * HD + c16 * 8);
    }
}

__global__ __launch_bounds__(ATHREADS, 2) void attn_mma()
{
    extern __shared__ __align__(16) char sma[];
    const uint32_t sb = smem_u32(sma);

    const int tid = threadIdx.x;
    const int lid = tid & 31;
    const int w   = tid >> 5;          // 0..3, each owns 32 q-rows
    const int bh  = blockIdx.y;
    const int q0  = blockIdx.x << 7;

    const size_t hoff = (size_t)bh * SEQ * HD;
    const __nv_bfloat16* Qhp = g_Qh + hoff;
    const __nv_bfloat16* Qlp = g_Ql + hoff;
    const __nv_bfloat16* Khp = g_Kh + hoff;
    const __nv_bfloat16* Klp = g_Kl + hoff;
    const __nv_bfloat16* Vhp = g_Vh + hoff;
    const __nv_bfloat16* Vlp = g_Vl + hoff;

    // ---- stage Q (128 x 64 bf16, hi+lo) into persistent smem region ----
#pragma unroll
    for (int it = 0; it < 16; it++) {
        int slot = tid + (it << 7);          // 0..2047
        int half = slot >> 10;               // 0:h 1:l
        int s2   = slot & 1023;
        int r    = s2 >> 3;                  // 0..127
        int c16  = s2 & 7;
        const __nv_bfloat16* base = half ? Qlp : Qhp;
        cp16(sb + half * QL_OFF + r * (AST * 2) + c16 * 16,
             base + (size_t)(q0 + r) * HD + c16 * 8);
    }
    attn_cp_kv(sb + KV_OFF, Khp, Klp, Vhp, Vlp, 0, tid);
    CP_COMMIT();

    float o[2][8][4];
#pragma unroll
    for (int i = 0; i < 2; i++)
#pragma unroll
        for (int j = 0; j < 8; j++)
#pragma unroll
            for (int v = 0; v < 4; v++) o[i][j][v] = 0.f;
    float mrow[2][2] = { { -1e30f, -1e30f }, { -1e30f, -1e30f } };
    float lrow[2][2] = { { 0.f, 0.f }, { 0.f, 0.f } };

#pragma unroll 1
    for (int kt = 0; kt < SEQ / 64; kt++) {
        CP_WAIT0();
        __syncthreads();    // stage kt%2 landed; all warps done reading kt-1

        if (kt + 1 < SEQ / 64) {
            attn_cp_kv(sb + KV_OFF + ((kt + 1) & 1) * ASTAGE,
                       Khp, Klp, Vhp, Vlp, kt + 1, tid);
            CP_COMMIT();
        }
        const uint32_t st = sb + KV_OFF + (kt & 1) * ASTAGE;

        // ---- S = Q @ K^T : 2 m-tiles x 8 n8-tiles, K-frag ping-pong ----
        float s[2][8][4];
#pragma unroll
        for (int i = 0; i < 2; i++)
#pragma unroll
            for (int j = 0; j < 8; j++)
#pragma unroll
                for (int v = 0; v < 4; v++) s[i][j][v] = 0.f;
#pragma unroll
        for (int k4 = 0; k4 < 4; k4++) {
            uint32_t q_h[2][4], q_l[2][4];
#pragma unroll
            for (int i = 0; i < 2; i++) {
                uint32_t qoff = (uint32_t)((w * 32 + i * 16 + (lid & 15)) * AST
                                           + k4 * 16 + (lid >> 4) * 8) * 2;
                ldsm4(q_h[i], sb + qoff);
                ldsm4(q_l[i], sb + QL_OFF + qoff);
            }
            const int rbase = (lid >> 4) & 1 ? 8 : 0;
            const int cc = k4 * 16 + ((lid >> 3) & 1) * 8;
            uint32_t kh4[2][4], kl4[2][4];
            {
                uint32_t off = (uint32_t)(((0 + (rbase >> 3)) * 8 + (lid & 7)) * AST + cc) * 2;
                // jp=0 row: (2*0 + hi-bit)*8 + lane
                off = (uint32_t)(((2 * 0 + ((lid >> 4) & 1)) * 8 + (lid & 7)) * AST + cc) * 2;
                ldsm4(kh4[0], st + off);
                ldsm4(kl4[0], st + ABUF + off);
            }
#pragma unroll
            for (int jp = 0; jp < 4; jp++) {
                const int cur = jp & 1, nxt = cur ^ 1;
                if (jp < 3) {
                    uint32_t off = (uint32_t)(((2 * (jp + 1) + ((lid >> 4) & 1)) * 8
                                               + (lid & 7)) * AST + cc) * 2;
                    ldsm4(kh4[nxt], st + off);
                    ldsm4(kl4[nxt], st + ABUF + off);
                }
                mma_bf16(s[0][2 * jp],     q_h[0], kh4[cur]);
                mma_bf16(s[1][2 * jp],     q_h[1], kh4[cur]);
                mma_bf16(s[0][2 * jp + 1], q_h[0], kh4[cur] + 2);
                mma_bf16(s[1][2 * jp + 1], q_h[1], kh4[cur] + 2);
                mma_bf16(s[0][2 * jp],     q_h[0], kl4[cur]);
                mma_bf16(s[1][2 * jp],     q_h[1], kl4[cur]);
                mma_bf16(s[0][2 * jp + 1], q_h[0], kl4[cur] + 2);
                mma_bf16(s[1][2 * jp + 1], q_h[1], kl4[cur] + 2);
                mma_bf16(s[0][2 * jp],     q_l[0], kh4[cur]);
                mma_bf16(s[1][2 * jp],     q_l[1], kh4[cur]);
                mma_bf16(s[0][2 * jp + 1], q_l[0], kh4[cur] + 2);
                mma_bf16(s[1][2 * jp + 1], q_l[1], kh4[cur] + 2);
            }
        }

        // ---- online softmax (per m-tile, per row-half) ----
#pragma unroll
        for (int i = 0; i < 2; i++) {
#pragma unroll
            for (int hh = 0; hh < 2; hh++) {
                float rm = -1e30f;
#pragma unroll
                for (int j = 0; j < 8; j++)
                    rm = fmaxf(rm, fmaxf(s[i][j][2 * hh], s[i][j][2 * hh + 1]));
                rm = fmaxf(rm, __shfl_xor_sync(0xffffffffu, rm, 1));
                rm = fmaxf(rm, __shfl_xor_sync(0xffffffffu, rm, 2));
                float mnew = fmaxf(mrow[i][hh], rm);
                float corr = __expf(mrow[i][hh] - mnew);
                mrow[i][hh] = mnew;
                float ls = lrow[i][hh] * corr;
#pragma unroll
                for (int j = 0; j < 8; j++) {
                    float p0 = __expf(s[i][j][2 * hh]     - mnew);
                    float p1 = __expf(s[i][j][2 * hh + 1] - mnew);
                    s[i][j][2 * hh] = p0; s[i][j][2 * hh + 1] = p1;
                    ls += p0 + p1;
                    o[i][j][2 * hh]     *= corr;
                    o[i][j][2 * hh + 1] *= corr;
                }
                lrow[i][hh] = ls;
            }
        }

        // ---- repack P into A-frags (hi/lo) ----
        uint32_t ph[2][4][4], pl[2][4][4];
#pragma unroll
        for (int i = 0; i < 2; i++) {
#pragma unroll
            for (int t = 0; t < 4; t++) {
#pragma unroll
                for (int half = 0; half < 2; half++) {
                    const float* sv = s[i][2 * t + half];
#pragma unroll
                    for (int hh = 0; hh < 2; hh++) {
                        float p0 = sv[2 * hh], p1 = sv[2 * hh + 1];
                        float h0 = bhi(p0), h1 = bhi(p1);
                        ph[i][t][2 * half + hh] = pack2(h0, h1);
                        pl[i][t][2 * half + hh] = pack2(p0 - h0, p1 - h1);
                    }
                }
            }
        }

        // ---- O += P @ V (V-frag ping-pong across t) ----
#pragma unroll
        for (int jp = 0; jp < 4; jp++) {
            const int c = (2 * jp + ((lid >> 4) & 1)) * 8;
            uint32_t vh4[2][4], vl4[2][4];
            {
                uint32_t off = (uint32_t)(((lid & 15)) * AST + c) * 2;   // t=0
                ldsm4t(vh4[0], st + 2 * ABUF + off);
                ldsm4t(vl4[0], st + 3 * ABUF + off);
            }
#pragma unroll
            for (int t = 0; t < 4; t++) {
                const int cur = t & 1, nxt = cur ^ 1;
                if (t < 3) {
                    uint32_t off = (uint32_t)(((t + 1) * 16 + (lid & 15)) * AST + c) * 2;
                    ldsm4t(vh4[nxt], st + 2 * ABUF + off);
                    ldsm4t(vl4[nxt], st + 3 * ABUF + off);
                }
                mma_bf16(o[0][2 * jp],     ph[0][t], vh4[cur]);
                mma_bf16(o[1][2 * jp],     ph[1][t], vh4[cur]);
                mma_bf16(o[0][2 * jp + 1], ph[0][t], vh4[cur] + 2);
                mma_bf16(o[1][2 * jp + 1], ph[1][t], vh4[cur] + 2);
                mma_bf16(o[0][2 * jp],     ph[0][t], vl4[cur]);
                mma_bf16(o[1][2 * jp],     ph[1][t], vl4[cur]);
                mma_bf16(o[0][2 * jp + 1], ph[0][t], vl4[cur] + 2);
                mma_bf16(o[1][2 * jp + 1], ph[1][t], vl4[cur] + 2);
                mma_bf16(o[0][2 * jp],     pl[0][t], vh4[cur]);
                mma_bf16(o[1][2 * jp],     pl[1][t], vh4[cur]);
                mma_bf16(o[0][2 * jp + 1], pl[0][t], vh4[cur] + 2);
                mma_bf16(o[1][2 * jp + 1], pl[1][t], vh4[cur] + 2);
            }
        }
    }

    // ---- epilogue: normalize, split hi/lo, write g_AOh/g_AOl [B,N,C] ----
    const int bb = bh >> 4, hd = bh & 15;
    const int qr = lid >> 2, qc = (lid & 3) << 1;
#pragma unroll
    for (int i = 0; i < 2; i++) {
#pragma unroll
        for (int hh = 0; hh < 2; hh++) {
            float lr = lrow[i][hh];
            lr += __shfl_xor_sync(0xffffffffu, lr, 1);
            lr += __shfl_xor_sync(0xffffffffu, lr, 2);
            float inv = 1.f / lr;
            int n = q0 + w * 32 + i * 16 + qr + hh * 8;
            size_t base = ((size_t)(bb * SEQ + n)) * DIMC + hd * HD;
#pragma unroll
            for (int j = 0; j < 8; j++) {
                float v0 = o[i][j][2 * hh] * inv, v1 = o[i][j][2 * hh + 1] * inv;
                float h0 = bhi(v0), h1 = bhi(v1);
                *reinterpret_cast<uint32_t*>(g_AOh + base + j * 8 + qc) = pack2(h0, h1);
                *reinterpret_cast<uint32_t*>(g_AOl + base + j * 8 + qc) = pack2(v0 - h0, v1 - h1);
            }
        }
    }
}

// ---------------------------------------------------------------------------
extern "C" void kernel_launch(void* const* d_in, const int* in_sizes, int n_in,
                              void* d_out, int out_size)
{
    const float* x      = (const float*)d_in[0];
    const float* w_qkv  = (const float*)d_in[1];
    const float* w_proj = (const float*)d_in[2];
    const float* b_proj = (const float*)d_in[3];
    float* out = (float*)d_out;

    __nv_bfloat16 *pXh, *pXl, *pWqh, *pWql, *pWph, *pWpl, *pAOh, *pAOl;
    cudaGetSymbolAddress((void**)&pXh,  g_Xh);
    cudaGetSymbolAddress((void**)&pXl,  g_Xl);
    cudaGetSymbolAddress((void**)&pWqh, g_Wqh);
    cudaGetSymbolAddress((void**)&pWql, g_Wql);
    cudaGetSymbolAddress((void**)&pWph, g_Wph);
    cudaGetSymbolAddress((void**)&pWpl, g_Wpl);
    cudaGetSymbolAddress((void**)&pAOh, g_AOh);
    cudaGetSymbolAddress((void**)&pAOl, g_AOl);

    cudaFuncSetAttribute(gemm_mma<0>,
                         cudaFuncAttributeMaxDynamicSharedMemorySize, SMEM_GEMM);
    cudaFuncSetAttribute(gemm_mma<1>,
                         cudaFuncAttributeMaxDynamicSharedMemorySize, SMEM_GEMM);
    cudaFuncSetAttribute(attn_mma,
                         cudaFuncAttributeMaxDynamicSharedMemorySize, SMEM_ATTN);

    // pre-split fp32 -> bf16 hi/lo
    int n4x = TOK * DIMC / 4, n4q = NQKV * DIMC / 4, n4p = DIMC * DIMC / 4;
    split_kernel<<<(n4x + 255) / 256, 256>>>(x, pXh, pXl, n4x);
    split_kernel<<<(n4q + 255) / 256, 256>>>(w_qkv, pWqh, pWql, n4q);
    split_kernel<<<(n4p + 255) / 256, 256>>>(w_proj, pWph, pWpl, n4p);

    dim3 g1(NQKV / 128, TOK / 128);      // (24, 64)
    gemm_mma<0><<<g1, 256, SMEM_GEMM>>>(pXh, pXl, pWqh, pWql,
                                        nullptr, nullptr, TOK, NQKV, DIMC);

    dim3 ga(SEQ / 128, BH);              // (16, 64)
    attn_mma<<<ga, ATHREADS, SMEM_ATTN>>>();

    dim3 g2(DIMC / 128, TOK / 128);      // (8, 64)
    gemm_mma<1><<<g2, 256, SMEM_GEMM>>>(pAOh, pAOl, pWph, pWpl,
                                        b_proj, out, TOK, DIMC, DIMC);
}